// round 1
// baseline (speedup 1.0000x reference)
#include <cuda_runtime.h>

// Problem constants
#define B_   64
#define C_   32
#define V_   512
#define L_   13
#define COUT 64
#define CCAT 224               // 7 * 32
#define M_ROWS (B_ * C_ * L_)  // 26624
#define ELEMS (M_ROWS * V_)    // 13631488

// Scratch: allocation-free rule -> __device__ globals.
__device__ float g_xt[ELEMS];        // x transposed to [(n,c,l), v]
__device__ float g_z[6][ELEMS];      // z1_a0, z2_a0, z1_a1, z2_a1, z1_a2, z2_a2

// ---------------------------------------------------------------------------
// 1) Transpose x[B,C,V,L] -> xt[(n*C+c)*L + l][v]
// ---------------------------------------------------------------------------
__global__ void transpose_kernel(const float* __restrict__ x, float* __restrict__ xt) {
    int idx = blockIdx.x * blockDim.x + threadIdx.x;
    if (idx >= ELEMS) return;
    int v  = idx & (V_ - 1);
    int r  = idx >> 9;          // / 512
    int l  = r % L_;
    int nc = r / L_;
    xt[idx] = x[(nc * V_ + v) * L_ + l];
}

// ---------------------------------------------------------------------------
// 2) SGEMM: C[M,512] = A[M,512] @ B[512,512], M = 26624. All tile-exact.
//    128x128 block tile, BK=16, 256 threads, 8x8 per thread.
// ---------------------------------------------------------------------------
#define BM 128
#define BN 128
#define BK 16
#define TM 8
#define TN 8

__global__ __launch_bounds__(256, 2)
void sgemm_prop(const float* __restrict__ A, const float* __restrict__ Bm,
                float* __restrict__ C) {
    const int N = 512, K = 512;
    __shared__ float As[BK][BM];
    __shared__ float Bs[BK][BN];

    const int tid = threadIdx.x;
    const int bm  = blockIdx.y * BM;
    const int bn  = blockIdx.x * BN;
    const int tx  = tid & 15;
    const int ty  = tid >> 4;

    float acc[TM][TN] = {};
    float af[TM], bf[TN];

    for (int kb = 0; kb < K; kb += BK) {
        // Load A tile: 128 rows x 16 k = 512 float4, 2 per thread.
        #pragma unroll
        for (int i = 0; i < 2; i++) {
            int f   = tid * 2 + i;
            int row = f >> 2;          // 4 float4 per row
            int k4  = (f & 3) * 4;
            float4 v = *(const float4*)(A + (bm + row) * K + kb + k4);
            As[k4 + 0][row] = v.x;
            As[k4 + 1][row] = v.y;
            As[k4 + 2][row] = v.z;
            As[k4 + 3][row] = v.w;
        }
        // Load B tile: 16 rows x 128 cols = 512 float4, 2 per thread.
        #pragma unroll
        for (int i = 0; i < 2; i++) {
            int f    = tid * 2 + i;
            int krow = f >> 5;         // 32 float4 per row
            int c4   = (f & 31) * 4;
            *(float4*)(&Bs[krow][c4]) =
                *(const float4*)(Bm + (kb + krow) * N + bn + c4);
        }
        __syncthreads();

        #pragma unroll
        for (int k = 0; k < BK; k++) {
            #pragma unroll
            for (int i = 0; i < TM; i++) af[i] = As[k][ty * TM + i];
            #pragma unroll
            for (int j = 0; j < TN; j++) bf[j] = Bs[k][tx * TN + j];
            #pragma unroll
            for (int i = 0; i < TM; i++)
                #pragma unroll
                for (int j = 0; j < TN; j++)
                    acc[i][j] = fmaf(af[i], bf[j], acc[i][j]);
        }
        __syncthreads();
    }

    #pragma unroll
    for (int i = 0; i < TM; i++) {
        int row = bm + ty * TM + i;
        #pragma unroll
        for (int j = 0; j < TN; j += 4) {
            float4 v = make_float4(acc[i][j], acc[i][j + 1], acc[i][j + 2], acc[i][j + 3]);
            *(float4*)(C + row * N + bn + tx * TN + j) = v;
        }
    }
}

// ---------------------------------------------------------------------------
// 3) Channel mix + output transpose:
//    out[n,o,v,l] = b[o] + sum_k W[o,k] * H_k[n, l*512+v]
//    H blocks (channel-concat order): xt, z0..z5.
//    Per block: one n, 64 output cols (all share the same l since 512%64==0),
//    64x64 tile, 256 threads, 4x4 per thread, BK=16 (K=224 = 14 iters).
// ---------------------------------------------------------------------------
__global__ __launch_bounds__(256)
void mix_kernel(const float* __restrict__ W, const float* __restrict__ bias,
                float* __restrict__ out) {
    __shared__ float Ws[16][64];
    __shared__ float Hs[16][68];   // pad cols to dodge conflicts

    const int tid     = threadIdx.x;
    const int n       = blockIdx.y;
    const int colBase = blockIdx.x * 64;    // col = l*512 + v
    const int tx = tid & 15;
    const int ty = tid >> 4;

    const float* bufs[7] = { g_xt, g_z[0], g_z[1], g_z[2], g_z[3], g_z[4], g_z[5] };

    float acc[4][4] = {};
    float wf[4], hf[4];

    for (int kb = 0; kb < CCAT; kb += 16) {
        // W chunk: 64 o x 16 k -> 256 float4, 1 per thread (vector along k).
        {
            int o  = tid >> 2;
            int kk = (tid & 3) * 4;
            float4 v = *(const float4*)(W + o * CCAT + kb + kk);
            Ws[kk + 0][o] = v.x;
            Ws[kk + 1][o] = v.y;
            Ws[kk + 2][o] = v.z;
            Ws[kk + 3][o] = v.w;
        }
        // H chunk: 16 k x 64 cols -> 256 float4, 1 per thread.
        {
            int k  = tid >> 4;
            int c4 = (tid & 15) * 4;
            int kg  = kb + k;
            int blk = kg >> 5;          // which of 7 channel blocks
            int c   = kg & 31;
            const float* src = bufs[blk] + (n * C_ + c) * (L_ * V_) + colBase + c4;
            float4 v = *(const float4*)src;
            Hs[k][c4 + 0] = v.x;
            Hs[k][c4 + 1] = v.y;
            Hs[k][c4 + 2] = v.z;
            Hs[k][c4 + 3] = v.w;
        }
        __syncthreads();

        #pragma unroll
        for (int k = 0; k < 16; k++) {
            #pragma unroll
            for (int i = 0; i < 4; i++) wf[i] = Ws[k][ty * 4 + i];
            #pragma unroll
            for (int j = 0; j < 4; j++) hf[j] = Hs[k][tx * 4 + j];
            #pragma unroll
            for (int i = 0; i < 4; i++)
                #pragma unroll
                for (int j = 0; j < 4; j++)
                    acc[i][j] = fmaf(wf[i], hf[j], acc[i][j]);
        }
        __syncthreads();
    }

    // Epilogue: col = l*512 + v; all 64 cols of this tile share one l.
    const int l     = colBase >> 9;
    const int vbase = colBase & (V_ - 1);
    #pragma unroll
    for (int i = 0; i < 4; i++) {
        int o = ty * 4 + i;
        float bo = bias[o];
        #pragma unroll
        for (int j = 0; j < 4; j++) {
            int v = vbase + tx * 4 + j;
            out[((n * COUT + o) * V_ + v) * L_ + l] = acc[i][j] + bo;
        }
    }
}

// ---------------------------------------------------------------------------
// Launcher. Inputs (metadata order): x, support0, support1, support2, W, b.
// ---------------------------------------------------------------------------
extern "C" void kernel_launch(void* const* d_in, const int* in_sizes, int n_in,
                              void* d_out, int out_size) {
    const float* x  = (const float*)d_in[0];
    const float* a0 = (const float*)d_in[1];
    const float* a1 = (const float*)d_in[2];
    const float* a2 = (const float*)d_in[3];
    const float* W  = (const float*)d_in[4];
    const float* b  = (const float*)d_in[5];
    float* out = (float*)d_out;

    float* xt;
    float* z[6];
    cudaGetSymbolAddress((void**)&xt, g_xt);
    cudaGetSymbolAddress((void**)&z[0], g_z);
    for (int i = 1; i < 6; i++) z[i] = z[0] + (size_t)i * ELEMS;

    // 1) transpose
    transpose_kernel<<<(ELEMS + 255) / 256, 256>>>(x, xt);

    // 2) six propagation GEMMs (order matches channel concat: x,z1a,z2a,z1b,z2b,z1c,z2c)
    dim3 ggrid(512 / BN, M_ROWS / BM);   // (4, 208)
    sgemm_prop<<<ggrid, 256>>>(xt,   a0, z[0]);
    sgemm_prop<<<ggrid, 256>>>(z[0], a0, z[1]);
    sgemm_prop<<<ggrid, 256>>>(xt,   a1, z[2]);
    sgemm_prop<<<ggrid, 256>>>(z[2], a1, z[3]);
    sgemm_prop<<<ggrid, 256>>>(xt,   a2, z[4]);
    sgemm_prop<<<ggrid, 256>>>(z[4], a2, z[5]);

    // 3) channel mix + output transpose
    dim3 mgrid((L_ * V_) / 64, B_);      // (104, 64)
    mix_kernel<<<mgrid, 256>>>(W, b, out);
}

// round 2
// speedup vs baseline: 1.0012x; 1.0012x over previous
#include <cuda_runtime.h>

// Problem constants
#define B_   64
#define C_   32
#define V_   512
#define L_   13
#define COUT 64
#define CCAT 224               // 7 * 32
#define M_ROWS (B_ * C_ * L_)  // 26624
#define ELEMS (M_ROWS * V_)    // 13631488

// Scratch: allocation-free rule -> __device__ globals.
__device__ float g_xt[ELEMS];        // x transposed to [(n,c,l), v]
__device__ float g_z[6][ELEMS];      // z1_a0, z2_a0, z1_a1, z2_a1, z1_a2, z2_a2

// ---------------------------------------------------------------------------
// 1) Transpose x[B,C,V,L] -> xt[(n*C+c)*L + l][v]
// ---------------------------------------------------------------------------
__global__ void transpose_kernel(const float* __restrict__ x, float* __restrict__ xt) {
    int idx = blockIdx.x * blockDim.x + threadIdx.x;
    if (idx >= ELEMS) return;
    int v  = idx & (V_ - 1);
    int r  = idx >> 9;          // / 512
    int l  = r % L_;
    int nc = r / L_;
    xt[idx] = x[(nc * V_ + v) * L_ + l];
}

// ---------------------------------------------------------------------------
// 2) SGEMM: C[M,512] = A[M,512] @ B[512,512], M = 26624. All tile-exact.
//    128x128 block tile, BK=16, 256 threads, 8x8 per thread.
// ---------------------------------------------------------------------------
#define BM 128
#define BN 128
#define BK 16
#define TM 8
#define TN 8

__global__ __launch_bounds__(256, 2)
void sgemm_prop(const float* __restrict__ A, const float* __restrict__ Bm,
                float* __restrict__ C) {
    const int N = 512, K = 512;
    __shared__ float As[BK][BM];
    __shared__ float Bs[BK][BN];

    const int tid = threadIdx.x;
    const int bm  = blockIdx.y * BM;
    const int bn  = blockIdx.x * BN;
    const int tx  = tid & 15;
    const int ty  = tid >> 4;

    float acc[TM][TN] = {};
    float af[TM], bf[TN];

    for (int kb = 0; kb < K; kb += BK) {
        // Load A tile: 128 rows x 16 k = 512 float4, 2 per thread.
        #pragma unroll
        for (int i = 0; i < 2; i++) {
            int f   = tid * 2 + i;
            int row = f >> 2;          // 4 float4 per row
            int k4  = (f & 3) * 4;
            float4 v = *(const float4*)(A + (bm + row) * K + kb + k4);
            As[k4 + 0][row] = v.x;
            As[k4 + 1][row] = v.y;
            As[k4 + 2][row] = v.z;
            As[k4 + 3][row] = v.w;
        }
        // Load B tile: 16 rows x 128 cols = 512 float4, 2 per thread.
        #pragma unroll
        for (int i = 0; i < 2; i++) {
            int f    = tid * 2 + i;
            int krow = f >> 5;         // 32 float4 per row
            int c4   = (f & 31) * 4;
            *(float4*)(&Bs[krow][c4]) =
                *(const float4*)(Bm + (kb + krow) * N + bn + c4);
        }
        __syncthreads();

        #pragma unroll
        for (int k = 0; k < BK; k++) {
            #pragma unroll
            for (int i = 0; i < TM; i++) af[i] = As[k][ty * TM + i];
            #pragma unroll
            for (int j = 0; j < TN; j++) bf[j] = Bs[k][tx * TN + j];
            #pragma unroll
            for (int i = 0; i < TM; i++)
                #pragma unroll
                for (int j = 0; j < TN; j++)
                    acc[i][j] = fmaf(af[i], bf[j], acc[i][j]);
        }
        __syncthreads();
    }

    #pragma unroll
    for (int i = 0; i < TM; i++) {
        int row = bm + ty * TM + i;
        #pragma unroll
        for (int j = 0; j < TN; j += 4) {
            float4 v = make_float4(acc[i][j], acc[i][j + 1], acc[i][j + 2], acc[i][j + 3]);
            *(float4*)(C + row * N + bn + tx * TN + j) = v;
        }
    }
}

// ---------------------------------------------------------------------------
// 3) Channel mix + output transpose:
//    out[n,o,v,l] = b[o] + sum_k W[o,k] * H_k[n, l*512+v]
//    H blocks (channel-concat order): xt, z0..z5.
//    Per block: one n, 64 output cols (all share the same l since 512%64==0),
//    64x64 tile, 256 threads, 4x4 per thread, BK=16 (K=224 = 14 iters).
// ---------------------------------------------------------------------------
__global__ __launch_bounds__(256)
void mix_kernel(const float* __restrict__ W, const float* __restrict__ bias,
                float* __restrict__ out) {
    __shared__ float Ws[16][64];
    __shared__ float Hs[16][68];   // pad cols to dodge conflicts

    const int tid     = threadIdx.x;
    const int n       = blockIdx.y;
    const int colBase = blockIdx.x * 64;    // col = l*512 + v
    const int tx = tid & 15;
    const int ty = tid >> 4;

    const float* bufs[7] = { g_xt, g_z[0], g_z[1], g_z[2], g_z[3], g_z[4], g_z[5] };

    float acc[4][4] = {};
    float wf[4], hf[4];

    for (int kb = 0; kb < CCAT; kb += 16) {
        // W chunk: 64 o x 16 k -> 256 float4, 1 per thread (vector along k).
        {
            int o  = tid >> 2;
            int kk = (tid & 3) * 4;
            float4 v = *(const float4*)(W + o * CCAT + kb + kk);
            Ws[kk + 0][o] = v.x;
            Ws[kk + 1][o] = v.y;
            Ws[kk + 2][o] = v.z;
            Ws[kk + 3][o] = v.w;
        }
        // H chunk: 16 k x 64 cols -> 256 float4, 1 per thread.
        {
            int k  = tid >> 4;
            int c4 = (tid & 15) * 4;
            int kg  = kb + k;
            int blk = kg >> 5;          // which of 7 channel blocks
            int c   = kg & 31;
            const float* src = bufs[blk] + (n * C_ + c) * (L_ * V_) + colBase + c4;
            float4 v = *(const float4*)src;
            Hs[k][c4 + 0] = v.x;
            Hs[k][c4 + 1] = v.y;
            Hs[k][c4 + 2] = v.z;
            Hs[k][c4 + 3] = v.w;
        }
        __syncthreads();

        #pragma unroll
        for (int k = 0; k < 16; k++) {
            #pragma unroll
            for (int i = 0; i < 4; i++) wf[i] = Ws[k][ty * 4 + i];
            #pragma unroll
            for (int j = 0; j < 4; j++) hf[j] = Hs[k][tx * 4 + j];
            #pragma unroll
            for (int i = 0; i < 4; i++)
                #pragma unroll
                for (int j = 0; j < 4; j++)
                    acc[i][j] = fmaf(wf[i], hf[j], acc[i][j]);
        }
        __syncthreads();
    }

    // Epilogue: col = l*512 + v; all 64 cols of this tile share one l.
    const int l     = colBase >> 9;
    const int vbase = colBase & (V_ - 1);
    #pragma unroll
    for (int i = 0; i < 4; i++) {
        int o = ty * 4 + i;
        float bo = bias[o];
        #pragma unroll
        for (int j = 0; j < 4; j++) {
            int v = vbase + tx * 4 + j;
            out[((n * COUT + o) * V_ + v) * L_ + l] = acc[i][j] + bo;
        }
    }
}

// ---------------------------------------------------------------------------
// Launcher. Inputs (metadata order): x, support0, support1, support2, W, b.
// ---------------------------------------------------------------------------
extern "C" void kernel_launch(void* const* d_in, const int* in_sizes, int n_in,
                              void* d_out, int out_size) {
    const float* x  = (const float*)d_in[0];
    const float* a0 = (const float*)d_in[1];
    const float* a1 = (const float*)d_in[2];
    const float* a2 = (const float*)d_in[3];
    const float* W  = (const float*)d_in[4];
    const float* b  = (const float*)d_in[5];
    float* out = (float*)d_out;

    float* xt;
    float* z[6];
    cudaGetSymbolAddress((void**)&xt, g_xt);
    cudaGetSymbolAddress((void**)&z[0], g_z);
    for (int i = 1; i < 6; i++) z[i] = z[0] + (size_t)i * ELEMS;

    // 1) transpose
    transpose_kernel<<<(ELEMS + 255) / 256, 256>>>(x, xt);

    // 2) six propagation GEMMs (order matches channel concat: x,z1a,z2a,z1b,z2b,z1c,z2c)
    dim3 ggrid(512 / BN, M_ROWS / BM);   // (4, 208)
    sgemm_prop<<<ggrid, 256>>>(xt,   a0, z[0]);
    sgemm_prop<<<ggrid, 256>>>(z[0], a0, z[1]);
    sgemm_prop<<<ggrid, 256>>>(xt,   a1, z[2]);
    sgemm_prop<<<ggrid, 256>>>(z[2], a1, z[3]);
    sgemm_prop<<<ggrid, 256>>>(xt,   a2, z[4]);
    sgemm_prop<<<ggrid, 256>>>(z[4], a2, z[5]);

    // 3) channel mix + output transpose
    dim3 mgrid((L_ * V_) / 64, B_);      // (104, 64)
    mix_kernel<<<mgrid, 256>>>(W, b, out);
}

// round 4
// speedup vs baseline: 1.3354x; 1.3338x over previous
#include <cuda_runtime.h>
#include <cuda_bf16.h>
#include <cstdint>

// ---------------------------------------------------------------- constants
#define B_    64
#define C_    32
#define V_    512
#define L_    13
#define COUT  64
#define CCAT  224
#define M_ROWS 26624            // B_*C_*L_
#define NB    3072              // 6 support-powers * 512
#define KBIG  1536              // 3 * 512 (hi | lo | hi)

// ---------------------------------------------------------------- scratch
__device__ float         g_xt [(size_t)M_ROWS * V_];       // 54.5 MB
__device__ float         g_z  [(size_t)M_ROWS * NB];       // 327 MB
__device__ __nv_bfloat16 g_Abf[(size_t)M_ROWS * KBIG];     // 81.8 MB
__device__ __nv_bfloat16 g_Bbf[(size_t)NB * KBIG];         // 9.4 MB
__device__ float         g_pow[3 * V_ * V_];               // 3.1 MB
__device__ float         g_tmp[(size_t)B_ * COUT * V_ * L_]; // 109 MB

// ---------------------------------------------------------------- PTX utils
__device__ __forceinline__ uint32_t smem_u32(const void* p) {
    uint32_t a;
    asm("{ .reg .u64 t; cvta.to.shared.u64 t, %1; cvt.u32.u64 %0, t; }" : "=r"(a) : "l"(p));
    return a;
}
__device__ __forceinline__ void cp_async16(uint32_t s, const void* g) {
    asm volatile("cp.async.cg.shared.global [%0], [%1], 16;" :: "r"(s), "l"(g));
}
__device__ __forceinline__ void ldsm4(uint32_t* r, uint32_t addr) {
    asm volatile("ldmatrix.sync.aligned.m8n8.x4.shared.b16 {%0,%1,%2,%3}, [%4];"
                 : "=r"(r[0]), "=r"(r[1]), "=r"(r[2]), "=r"(r[3]) : "r"(addr));
}
__device__ __forceinline__ void mma16816(float* d, const uint32_t* a, uint32_t b0, uint32_t b1) {
    asm volatile(
        "mma.sync.aligned.m16n8k16.row.col.f32.bf16.bf16.f32 "
        "{%0,%1,%2,%3}, {%4,%5,%6,%7}, {%8,%9}, {%0,%1,%2,%3};"
        : "+f"(d[0]), "+f"(d[1]), "+f"(d[2]), "+f"(d[3])
        : "r"(a[0]), "r"(a[1]), "r"(a[2]), "r"(a[3]), "r"(b0), "r"(b1));
}
#define SW128(off) ((off) ^ (((off) >> 3) & 0x70))

// ---------------------------------------------------------------- 1) a^2 (fp32)
__global__ __launch_bounds__(256)
void pow_kernel(const float* __restrict__ a0, const float* __restrict__ a1,
                const float* __restrict__ a2, float* __restrict__ out) {
    const float* A = (blockIdx.z == 0) ? a0 : (blockIdx.z == 1 ? a1 : a2);
    float* Cc = out + (size_t)blockIdx.z * V_ * V_;
    __shared__ float As[16][64];
    __shared__ float Bs[16][68];
    const int tid = threadIdx.x;
    const int bm = blockIdx.y * 64, bn = blockIdx.x * 64;
    const int tx = tid & 15, ty = tid >> 4;
    float acc[4][4] = {};
    for (int kb = 0; kb < 512; kb += 16) {
        float4 va = *(const float4*)(A + (size_t)(bm + (tid >> 2)) * 512 + kb + (tid & 3) * 4);
        As[(tid & 3) * 4 + 0][tid >> 2] = va.x;
        As[(tid & 3) * 4 + 1][tid >> 2] = va.y;
        As[(tid & 3) * 4 + 2][tid >> 2] = va.z;
        As[(tid & 3) * 4 + 3][tid >> 2] = va.w;
        *(float4*)&Bs[tid >> 4][(tid & 15) * 4] =
            *(const float4*)(A + (size_t)(kb + (tid >> 4)) * 512 + bn + (tid & 15) * 4);
        __syncthreads();
        #pragma unroll
        for (int k = 0; k < 16; k++) {
            float wf[4], hf[4];
            #pragma unroll
            for (int i = 0; i < 4; i++) wf[i] = As[k][ty * 4 + i];
            #pragma unroll
            for (int j = 0; j < 4; j++) hf[j] = Bs[k][tx * 4 + j];
            #pragma unroll
            for (int i = 0; i < 4; i++)
                #pragma unroll
                for (int j = 0; j < 4; j++) acc[i][j] = fmaf(wf[i], hf[j], acc[i][j]);
        }
        __syncthreads();
    }
    #pragma unroll
    for (int i = 0; i < 4; i++)
        #pragma unroll
        for (int j = 0; j < 4; j++)
            Cc[(size_t)(bm + ty * 4 + i) * 512 + bn + tx * 4 + j] = acc[i][j];
}

// ---------------------------------------------------------------- 2) xt + A' (hi|lo|hi)
__global__ __launch_bounds__(256)
void build_A(const float* __restrict__ x, float* __restrict__ xt,
             __nv_bfloat16* __restrict__ Abf) {
    __shared__ float s[V_ * L_];               // one (n,c) slab
    const int nc = blockIdx.x;
    const int tid = threadIdx.x;
    const float* slab = x + (size_t)nc * (V_ * L_);
    for (int i = tid; i < V_ * L_; i += 256) s[i] = slab[i];
    __syncthreads();
    for (int e = tid; e < V_ * L_; e += 256) {
        int l = e >> 9, v = e & 511;
        float val = s[v * L_ + l];
        size_t row = (size_t)nc * L_ + l;
        xt[row * V_ + v] = val;
        __nv_bfloat16 hi = __float2bfloat16(val);
        __nv_bfloat16 lo = __float2bfloat16(val - __bfloat162float(hi));
        __nv_bfloat16* ar = Abf + row * KBIG;
        ar[v] = hi; ar[512 + v] = lo; ar[1024 + v] = hi;
    }
}

// ---------------------------------------------------------------- 3) B' (hi|hi|lo)
__global__ __launch_bounds__(256)
void build_B(const float* __restrict__ a0, const float* __restrict__ a1,
             const float* __restrict__ a2, const float* __restrict__ pw,
             __nv_bfloat16* __restrict__ Bbf) {
    int idx = blockIdx.x * 256 + threadIdx.x;   // over NB*512
    if (idx >= NB * 512) return;
    int v = idx & 511;
    int j = idx >> 9;                // B' row: p*512 + w
    int p = j >> 9;
    int w = j & 511;
    const float* P = (p & 1) ? (pw + (size_t)(p >> 1) * V_ * V_)
                             : (p == 0 ? a0 : (p == 2 ? a1 : a2));
    float val = P[(size_t)v * 512 + w];
    __nv_bfloat16 hi = __float2bfloat16(val);
    __nv_bfloat16 lo = __float2bfloat16(val - __bfloat162float(hi));
    __nv_bfloat16* br = Bbf + (size_t)j * KBIG;
    br[v] = hi; br[512 + v] = hi; br[1024 + v] = lo;
}

// ---------------------------------------------------------------- 4) HMMA GEMM
// z[26624,3072] = A'[26624,1536] @ B'[3072,1536]^T, fp32 acc.
// 512 thr, BM=128, BN=256, BK=64, 3-stage cp.async, warp tile 32x64.
#define BMg 128
#define BNg 256
#define BKg 64
#define NSTG 3
#define STG_A (BMg * BKg * 2)              // 16384 B
#define STG_B (BNg * BKg * 2)              // 32768 B
#define STG_BYTES (STG_A + STG_B)          // 49152 B
#define GEMM_SMEM (NSTG * STG_BYTES)       // 147456 B
#define KITERS (KBIG / BKg)                // 24

__global__ __launch_bounds__(512, 1)
void mma_gemm(const __nv_bfloat16* __restrict__ A, const __nv_bfloat16* __restrict__ Bm,
              float* __restrict__ Cm) {
    extern __shared__ char smem[];
    const uint32_t sb = smem_u32(smem);
    const int tid = threadIdx.x;
    const int wid = tid >> 5, lane = tid & 31;
    const int bm = blockIdx.x * BMg;
    const int bn = blockIdx.y * BNg;
    const int wm = wid & 3;        // M warp index (4)
    const int wn = wid >> 2;       // N warp index (4)

    float acc[2][8][4];
    #pragma unroll
    for (int i = 0; i < 2; i++)
        #pragma unroll
        for (int j = 0; j < 8; j++)
            #pragma unroll
            for (int q = 0; q < 4; q++) acc[i][j][q] = 0.f;

    auto load_stage = [&](int slot, int it) {
        const uint32_t abase = sb + slot * STG_BYTES;
        const uint32_t bbase = abase + STG_A;
        const __nv_bfloat16* Ag = A + (size_t)bm * KBIG + it * BKg;
        const __nv_bfloat16* Bg = Bm + (size_t)bn * KBIG + it * BKg;
        #pragma unroll
        for (int i = 0; i < 2; i++) {              // A: 1024 x 16B
            int c = tid + i * 512;
            int row = c >> 3, c16 = c & 7;
            uint32_t off = (uint32_t)(row * 128 + c16 * 16);
            cp_async16(abase + SW128(off), Ag + (size_t)row * KBIG + c16 * 8);
        }
        #pragma unroll
        for (int i = 0; i < 4; i++) {              // B: 2048 x 16B
            int c = tid + i * 512;
            int row = c >> 3, c16 = c & 7;
            uint32_t off = (uint32_t)(row * 128 + c16 * 16);
            cp_async16(bbase + SW128(off), Bg + (size_t)row * KBIG + c16 * 8);
        }
        asm volatile("cp.async.commit_group;" ::: "memory");
    };

    load_stage(0, 0);
    load_stage(1, 1);

    for (int it = 0; it < KITERS; it++) {
        if (it + 2 < KITERS) load_stage((it + 2) % NSTG, it + 2);

        int rem = KITERS - 1 - it;
        if (rem >= 2)      asm volatile("cp.async.wait_group 2;" ::: "memory");
        else if (rem == 1) asm volatile("cp.async.wait_group 1;" ::: "memory");
        else               asm volatile("cp.async.wait_group 0;" ::: "memory");
        __syncthreads();

        const uint32_t abase = sb + (it % NSTG) * STG_BYTES;
        const uint32_t bbase = abase + STG_A;
        const int lrow = lane & 15;
        const int lkh  = (lane >> 4) << 3;     // k half: 0 or 8

        #pragma unroll
        for (int ks = 0; ks < 4; ks++) {
            const int k0 = ks * 16;
            uint32_t a_regs[2][4];
            #pragma unroll
            for (int mf = 0; mf < 2; mf++) {
                int row  = wm * 32 + mf * 16 + lrow;
                int kcol = k0 + lkh;
                ldsm4(a_regs[mf], abase + SW128((uint32_t)(row * 128 + kcol * 2)));
            }
            uint32_t b_regs[4][4];
            #pragma unroll
            for (int nq = 0; nq < 4; nq++) {
                int row  = wn * 64 + nq * 16 + lrow;
                int kcol = k0 + lkh;
                ldsm4(b_regs[nq], bbase + SW128((uint32_t)(row * 128 + kcol * 2)));
            }
            #pragma unroll
            for (int mf = 0; mf < 2; mf++)
                #pragma unroll
                for (int nq = 0; nq < 4; nq++) {
                    mma16816(acc[mf][nq * 2 + 0], a_regs[mf], b_regs[nq][0], b_regs[nq][2]);
                    mma16816(acc[mf][nq * 2 + 1], a_regs[mf], b_regs[nq][1], b_regs[nq][3]);
                }
        }
        __syncthreads();
    }

    // epilogue: direct float2 stores (32B sectors fully used per lane quad)
    const int gid = lane >> 2, tig = lane & 3;
    #pragma unroll
    for (int mf = 0; mf < 2; mf++) {
        int r0 = bm + wm * 32 + mf * 16 + gid;
        #pragma unroll
        for (int nf = 0; nf < 8; nf++) {
            int c = bn + wn * 64 + nf * 8 + tig * 2;
            float* d = acc[mf][nf];
            *(float2*)(Cm + (size_t)r0 * NB + c)       = make_float2(d[0], d[1]);
            *(float2*)(Cm + (size_t)(r0 + 8) * NB + c) = make_float2(d[2], d[3]);
        }
    }
}

// ---------------------------------------------------------------- 5) channel mix -> tmp (v-contig)
__global__ __launch_bounds__(256)
void mix_kernel(const float* __restrict__ W, const float* __restrict__ bias,
                float* __restrict__ tmp) {
    __shared__ float Ws[16][64];
    __shared__ float Hs[16][132];

    const int tid     = threadIdx.x;
    const int n       = blockIdx.y;
    const int colBase = blockIdx.x * 128;     // 52 x-blocks, never crosses l
    const int tx = tid & 31;
    const int ty = tid >> 5;
    const int l  = colBase >> 9;
    const int vb = colBase & (V_ - 1);

    float acc[8][4] = {};

    for (int kb = 0; kb < CCAT; kb += 16) {
        {   // W chunk: 64 o x 16 k, transposed into Ws[k][o]
            int o  = tid >> 2;
            int kk = (tid & 3) * 4;
            float4 v = *(const float4*)(W + o * CCAT + kb + kk);
            Ws[kk + 0][o] = v.x; Ws[kk + 1][o] = v.y;
            Ws[kk + 2][o] = v.z; Ws[kk + 3][o] = v.w;
        }
        #pragma unroll
        for (int i = 0; i < 2; i++) {   // H chunk: 16 k x 128 cols
            int c  = tid + i * 256;
            int k  = c >> 5;
            int c4 = (c & 31) * 4;
            int kg  = kb + k;
            int blk = kg >> 5;
            int ch  = kg & 31;
            size_t row = ((size_t)n * C_ + ch) * L_ + l;
            const float* src = (blk == 0)
                ? g_xt + row * V_ + vb + c4
                : g_z  + row * NB + (size_t)(blk - 1) * 512 + vb + c4;
            *(float4*)&Hs[k][c4] = *(const float4*)src;
        }
        __syncthreads();

        #pragma unroll
        for (int k = 0; k < 16; k++) {
            float4 w0 = *(float4*)&Ws[k][ty * 8];
            float4 w1 = *(float4*)&Ws[k][ty * 8 + 4];
            float4 h  = *(float4*)&Hs[k][tx * 4];
            float wf[8] = {w0.x, w0.y, w0.z, w0.w, w1.x, w1.y, w1.z, w1.w};
            float hf[4] = {h.x, h.y, h.z, h.w};
            #pragma unroll
            for (int i = 0; i < 8; i++)
                #pragma unroll
                for (int j = 0; j < 4; j++)
                    acc[i][j] = fmaf(wf[i], hf[j], acc[i][j]);
        }
        __syncthreads();
    }

    #pragma unroll
    for (int i = 0; i < 8; i++) {
        int o = ty * 8 + i;
        float bo = bias[o];
        float4 v4 = make_float4(acc[i][0] + bo, acc[i][1] + bo,
                                acc[i][2] + bo, acc[i][3] + bo);
        *(float4*)(tmp + ((size_t)n * COUT + o) * (V_ * L_) + colBase + tx * 4) = v4;
    }
}

// ---------------------------------------------------------------- 6) tmp[l*512+v] -> out[v*13+l]
__global__ __launch_bounds__(128)
void out_transpose(const float* __restrict__ tmp, float* __restrict__ out) {
    __shared__ float s[V_ * L_];
    const int no  = blockIdx.x;                 // n*64 + o
    const int tid = threadIdx.x;
    const float* src = tmp + (size_t)no * (V_ * L_);
    for (int i = tid; i < V_ * L_; i += 128) s[i] = src[i];
    __syncthreads();
    float* dst = out + (size_t)no * (V_ * L_);
    #pragma unroll
    for (int i = 0; i < 4; i++) {
        int v = tid + i * 128;
        #pragma unroll
        for (int l = 0; l < L_; l++)
            dst[v * L_ + l] = s[l * V_ + v];
    }
}

// ---------------------------------------------------------------- launcher
extern "C" void kernel_launch(void* const* d_in, const int* in_sizes, int n_in,
                              void* d_out, int out_size) {
    const float* x  = (const float*)d_in[0];
    const float* a0 = (const float*)d_in[1];
    const float* a1 = (const float*)d_in[2];
    const float* a2 = (const float*)d_in[3];
    const float* W  = (const float*)d_in[4];
    const float* b  = (const float*)d_in[5];
    float* out = (float*)d_out;

    float *xt, *z, *pw, *tmp;
    __nv_bfloat16 *Abf, *Bbf;
    cudaGetSymbolAddress((void**)&xt,  g_xt);
    cudaGetSymbolAddress((void**)&z,   g_z);
    cudaGetSymbolAddress((void**)&pw,  g_pow);
    cudaGetSymbolAddress((void**)&tmp, g_tmp);
    cudaGetSymbolAddress((void**)&Abf, g_Abf);
    cudaGetSymbolAddress((void**)&Bbf, g_Bbf);

    cudaFuncSetAttribute(mma_gemm, cudaFuncAttributeMaxDynamicSharedMemorySize, GEMM_SMEM);

    pow_kernel<<<dim3(8, 8, 3), 256>>>(a0, a1, a2, pw);
    build_A<<<B_ * C_, 256>>>(x, xt, Abf);
    build_B<<<(NB * 512) / 256, 256>>>(a0, a1, a2, pw, Bbf);

    mma_gemm<<<dim3(M_ROWS / BMg, NB / BNg), 512, GEMM_SMEM>>>(Abf, Bbf, z);

    mix_kernel<<<dim3((L_ * V_) / 128, B_), 256>>>(W, b, tmp);
    out_transpose<<<B_ * COUT, 128>>>(tmp, out);
}

// round 6
// speedup vs baseline: 2.1359x; 1.5995x over previous
#include <cuda_runtime.h>
#include <cuda_bf16.h>
#include <cstdint>

// ---------------------------------------------------------------- constants
#define B_    64
#define C_    32
#define V_    512
#define L_    13
#define COUT  64
#define M_ROWS 26624            // B_*C_*L_   (rows ordered (n,l,c), c innermost)
#define NB    3072              // 6 support-powers * 512
#define KBIG  1536              // 3 * 512 (hi | lo | hi)
#define NLW   425984            // 832 (n,l) * 512 w   — zT rows
#define ZTC   448               // zT cols: [hi(224) | lo(224)]

// ---------------------------------------------------------------- scratch
__device__ __nv_bfloat16 g_Abf[(size_t)M_ROWS * KBIG];     // 81.8 MB
__device__ __nv_bfloat16 g_Bbf[(size_t)NB * KBIG];         // 9.4 MB
__device__ __nv_bfloat16 g_zT [(size_t)NLW * ZTC];         // 381.7 MB
__device__ __nv_bfloat16 g_Wp [(size_t)COUT * ZTC];        // W' = [hi|lo]
__device__ float         g_pow[3 * V_ * V_];               // a^2
__device__ float         g_tmp[(size_t)B_ * COUT * L_ * V_]; // [n][o][l][v] 109 MB

// ---------------------------------------------------------------- PTX utils
__device__ __forceinline__ uint32_t smem_u32(const void* p) {
    uint32_t a;
    asm("{ .reg .u64 t; cvta.to.shared.u64 t, %1; cvt.u32.u64 %0, t; }" : "=r"(a) : "l"(p));
    return a;
}
__device__ __forceinline__ void cp_async16(uint32_t s, const void* g) {
    asm volatile("cp.async.cg.shared.global [%0], [%1], 16;" :: "r"(s), "l"(g));
}
__device__ __forceinline__ void ldsm4(uint32_t* r, uint32_t addr) {
    asm volatile("ldmatrix.sync.aligned.m8n8.x4.shared.b16 {%0,%1,%2,%3}, [%4];"
                 : "=r"(r[0]), "=r"(r[1]), "=r"(r[2]), "=r"(r[3]) : "r"(addr));
}
__device__ __forceinline__ void mma16816(float* d, const uint32_t* a, uint32_t b0, uint32_t b1) {
    asm volatile(
        "mma.sync.aligned.m16n8k16.row.col.f32.bf16.bf16.f32 "
        "{%0,%1,%2,%3}, {%4,%5,%6,%7}, {%8,%9}, {%0,%1,%2,%3};"
        : "+f"(d[0]), "+f"(d[1]), "+f"(d[2]), "+f"(d[3])
        : "r"(a[0]), "r"(a[1]), "r"(a[2]), "r"(a[3]), "r"(b0), "r"(b1));
}
#define SW128(off) ((off) ^ (((off) >> 3) & 0x70))

__device__ __forceinline__ uint16_t bfbits(float f) {
    __nv_bfloat16 h = __float2bfloat16(f);
    return *reinterpret_cast<uint16_t*>(&h);
}
__device__ __forceinline__ float bf2f(uint16_t u) {
    __nv_bfloat16 h = *reinterpret_cast<__nv_bfloat16*>(&u);
    return __bfloat162float(h);
}

// K-chunk schedules for the mix GEMM 3-term split:
// A side picks hi (cols 0..223) for chunks 0..13, lo (224..447) for 14..20.
// B side pairs so that products are hh (0-6), lh (7-13), hl (14-20).
__device__ __forceinline__ int acol_of(int i) {
    return (i < 14) ? (i % 7) * 32 : 224 + (i - 14) * 32;
}
__device__ __forceinline__ int bcol_of(int i) {
    return (i < 7) ? i * 32 : (i < 14 ? 224 + (i - 7) * 32 : (i - 14) * 32);
}

// ---------------------------------------------------------------- 1) a^2 (fp32)
__global__ __launch_bounds__(256)
void pow_kernel(const float* __restrict__ a0, const float* __restrict__ a1,
                const float* __restrict__ a2, float* __restrict__ out) {
    const float* A = (blockIdx.z == 0) ? a0 : (blockIdx.z == 1 ? a1 : a2);
    float* Cc = out + (size_t)blockIdx.z * V_ * V_;
    __shared__ float As[16][64];
    __shared__ float Bs[16][68];
    const int tid = threadIdx.x;
    const int bm = blockIdx.y * 64, bn = blockIdx.x * 64;
    const int tx = tid & 15, ty = tid >> 4;
    float acc[4][4] = {};
    for (int kb = 0; kb < 512; kb += 16) {
        float4 va = *(const float4*)(A + (size_t)(bm + (tid >> 2)) * 512 + kb + (tid & 3) * 4);
        As[(tid & 3) * 4 + 0][tid >> 2] = va.x;
        As[(tid & 3) * 4 + 1][tid >> 2] = va.y;
        As[(tid & 3) * 4 + 2][tid >> 2] = va.z;
        As[(tid & 3) * 4 + 3][tid >> 2] = va.w;
        *(float4*)&Bs[tid >> 4][(tid & 15) * 4] =
            *(const float4*)(A + (size_t)(kb + (tid >> 4)) * 512 + bn + (tid & 15) * 4);
        __syncthreads();
        #pragma unroll
        for (int k = 0; k < 16; k++) {
            float wf[4], hf[4];
            #pragma unroll
            for (int i = 0; i < 4; i++) wf[i] = As[k][ty * 4 + i];
            #pragma unroll
            for (int j = 0; j < 4; j++) hf[j] = Bs[k][tx * 4 + j];
            #pragma unroll
            for (int i = 0; i < 4; i++)
                #pragma unroll
                for (int j = 0; j < 4; j++) acc[i][j] = fmaf(wf[i], hf[j], acc[i][j]);
        }
        __syncthreads();
    }
    #pragma unroll
    for (int i = 0; i < 4; i++)
        #pragma unroll
        for (int j = 0; j < 4; j++)
            Cc[(size_t)(bm + ty * 4 + i) * 512 + bn + tx * 4 + j] = acc[i][j];
}

// ---------------------------------------------------------------- 2) A' rows (n,l,c)
__global__ __launch_bounds__(256)
void build_A(const float* __restrict__ x, __nv_bfloat16* __restrict__ Abf) {
    __shared__ float s[V_ * L_];
    const int nc = blockIdx.x;              // n*32 + c
    const int n = nc >> 5, c = nc & 31;
    const int tid = threadIdx.x;
    const float* slab = x + (size_t)nc * (V_ * L_);
    for (int i = tid; i < V_ * L_; i += 256) s[i] = slab[i];
    __syncthreads();
    for (int e = tid; e < V_ * L_; e += 256) {
        int l = e >> 9, v = e & 511;
        float val = s[v * L_ + l];
        size_t m = ((size_t)n * L_ + l) * 32 + c;
        uint16_t hi = bfbits(val);
        uint16_t lo = bfbits(val - bf2f(hi));
        uint16_t* ar = (uint16_t*)(Abf + m * KBIG);
        ar[v] = hi; ar[512 + v] = lo; ar[1024 + v] = hi;
    }
}

// ---------------------------------------------------------------- 3) B' (hi|hi|lo)
__global__ __launch_bounds__(256)
void build_B(const float* __restrict__ a0, const float* __restrict__ a1,
             const float* __restrict__ a2, const float* __restrict__ pw,
             __nv_bfloat16* __restrict__ Bbf) {
    int idx = blockIdx.x * 256 + threadIdx.x;
    if (idx >= NB * 512) return;
    int v = idx & 511;
    int j = idx >> 9;                // B' row: p*512 + w
    int p = j >> 9;
    int w = j & 511;
    const float* P = (p & 1) ? (pw + (size_t)(p >> 1) * V_ * V_)
                             : (p == 0 ? a0 : (p == 2 ? a1 : a2));
    float val = P[(size_t)v * 512 + w];
    uint16_t hi = bfbits(val);
    uint16_t lo = bfbits(val - bf2f(hi));
    uint16_t* br = (uint16_t*)(Bbf + (size_t)j * KBIG);
    br[v] = hi; br[512 + v] = hi; br[1024 + v] = lo;
}

// ---------------------------------------------------------------- 4) seed zT chan-block 0 (x)
__global__ __launch_bounds__(256)
void seed_zT(const __nv_bfloat16* __restrict__ Abf, __nv_bfloat16* __restrict__ zT) {
    extern __shared__ uint16_t s16[];       // [32][1024]: hi then lo per c-row
    const int nl = blockIdx.x;
    const int tid = threadIdx.x;
    for (int i = tid; i < 32 * 512; i += 256) {     // copy as u32 (1024 bf16 per row)
        int c = i >> 9, kk = i & 511;
        const uint32_t* pa = (const uint32_t*)(Abf + ((size_t)nl * 32 + c) * KBIG);
        ((uint32_t*)s16)[c * 512 + kk] = pa[kk];
    }
    __syncthreads();
    #pragma unroll
    for (int rep = 0; rep < 2; rep++) {
        int v = tid + rep * 256;
        uint32_t hi[16], lo[16];
        #pragma unroll
        for (int i = 0; i < 16; i++) {
            uint32_t h0 = s16[(2*i) * 1024 + v],       h1 = s16[(2*i+1) * 1024 + v];
            uint32_t l0 = s16[(2*i) * 1024 + 512 + v], l1 = s16[(2*i+1) * 1024 + 512 + v];
            hi[i] = h0 | (h1 << 16);
            lo[i] = l0 | (l1 << 16);
        }
        char* dst = (char*)zT + ((size_t)nl * 512 + v) * (ZTC * 2);
        #pragma unroll
        for (int i = 0; i < 4; i++) {
            *(uint4*)(dst + i * 16)       = *(uint4*)(hi + i * 4);
            *(uint4*)(dst + 448 + i * 16) = *(uint4*)(lo + i * 4);
        }
    }
}

// ---------------------------------------------------------------- 5) GEMM1 (HMMA)
#define BMg 128
#define BNg 128
#define BKg 64
#define NSTG 3
#define STG_A (BMg * BKg * 2)              // 16384 B
#define STG_B (BNg * BKg * 2)              // 16384 B
#define STG_BYTES (STG_A + STG_B)          // 32768 B
#define GEMM_SMEM (NSTG * STG_BYTES)       // 98304 B
#define KITERS (KBIG / BKg)                // 24

__global__ __launch_bounds__(256, 2)
void mma_gemm(const __nv_bfloat16* __restrict__ A, const __nv_bfloat16* __restrict__ Bm,
              __nv_bfloat16* __restrict__ zT) {
    extern __shared__ char smem[];
    const uint32_t sb = smem_u32(smem);
    const int tid = threadIdx.x;
    const int wid = tid >> 5, lane = tid & 31;
    const int bm = blockIdx.x * BMg;
    const int bn = blockIdx.y * BNg;
    const int wm = wid & 3;        // 4 M-warps
    const int wn = wid >> 2;       // 2 N-warps

    float acc[2][8][4];
    #pragma unroll
    for (int i = 0; i < 2; i++)
        #pragma unroll
        for (int j = 0; j < 8; j++)
            #pragma unroll
            for (int q = 0; q < 4; q++) acc[i][j][q] = 0.f;

    auto load_stage = [&](int slot, int it) {
        const uint32_t abase = sb + slot * STG_BYTES;
        const uint32_t bbase = abase + STG_A;
        const __nv_bfloat16* Ag = A + (size_t)bm * KBIG + it * BKg;
        const __nv_bfloat16* Bg = Bm + (size_t)bn * KBIG + it * BKg;
        #pragma unroll
        for (int i = 0; i < 4; i++) {              // A: 1024 x 16B
            int c = tid + i * 256;
            int row = c >> 3, c16 = c & 7;
            uint32_t off = (uint32_t)(row * 128 + c16 * 16);
            cp_async16(abase + SW128(off), Ag + (size_t)row * KBIG + c16 * 8);
        }
        #pragma unroll
        for (int i = 0; i < 4; i++) {              // B: 1024 x 16B
            int c = tid + i * 256;
            int row = c >> 3, c16 = c & 7;
            uint32_t off = (uint32_t)(row * 128 + c16 * 16);
            cp_async16(bbase + SW128(off), Bg + (size_t)row * KBIG + c16 * 8);
        }
        asm volatile("cp.async.commit_group;" ::: "memory");
    };

    load_stage(0, 0);
    load_stage(1, 1);

    for (int it = 0; it < KITERS; it++) {
        if (it + 2 < KITERS) load_stage((it + 2) % NSTG, it + 2);

        int rem = KITERS - 1 - it;
        if (rem >= 2)      asm volatile("cp.async.wait_group 2;" ::: "memory");
        else if (rem == 1) asm volatile("cp.async.wait_group 1;" ::: "memory");
        else               asm volatile("cp.async.wait_group 0;" ::: "memory");
        __syncthreads();

        const uint32_t abase = sb + (it % NSTG) * STG_BYTES;
        const uint32_t bbase = abase + STG_A;
        const int lrow = lane & 15;
        const int lkh  = (lane >> 4) << 3;

        #pragma unroll
        for (int ks = 0; ks < 4; ks++) {
            const int k0 = ks * 16;
            uint32_t a_regs[2][4];
            #pragma unroll
            for (int mf = 0; mf < 2; mf++) {
                int row = wm * 32 + mf * 16 + lrow;
                ldsm4(a_regs[mf], abase + SW128((uint32_t)(row * 128 + (k0 + lkh) * 2)));
            }
            uint32_t b_regs[4][4];
            #pragma unroll
            for (int nq = 0; nq < 4; nq++) {
                int row = wn * 64 + nq * 16 + lrow;
                ldsm4(b_regs[nq], bbase + SW128((uint32_t)(row * 128 + (k0 + lkh) * 2)));
            }
            #pragma unroll
            for (int mf = 0; mf < 2; mf++)
                #pragma unroll
                for (int nq = 0; nq < 4; nq++) {
                    mma16816(acc[mf][nq * 2 + 0], a_regs[mf], b_regs[nq][0], b_regs[nq][2]);
                    mma16816(acc[mf][nq * 2 + 1], a_regs[mf], b_regs[nq][1], b_regs[nq][3]);
                }
        }
        __syncthreads();
    }

    // ---- epilogue: acc -> smem fp32 [128][129] -> zT bf16 hi/lo, c-transposed
    float* s = (float*)smem;                 // 128*129*4 = 66048 <= 98304
    const int gid = lane >> 2, tig = lane & 3;
    #pragma unroll
    for (int mf = 0; mf < 2; mf++) {
        int r0 = wm * 32 + mf * 16 + gid;
        #pragma unroll
        for (int nf = 0; nf < 8; nf++) {
            int cc = wn * 64 + nf * 8 + tig * 2;
            float* d = acc[mf][nf];
            s[r0 * 129 + cc] = d[0];       s[r0 * 129 + cc + 1] = d[1];
            s[(r0 + 8) * 129 + cc] = d[2]; s[(r0 + 8) * 129 + cc + 1] = d[3];
        }
    }
    __syncthreads();

    const int p = bn >> 9;                  // support-power block
    const int wbase = bn & 511;
    const int nlbase = bm >> 5;             // bm/32: first of 4 (n,l) groups
    #pragma unroll
    for (int rep = 0; rep < 2; rep++) {
        int rw = tid + rep * 256;           // 0..511
        int nlg = rw >> 7, w = rw & 127;
        uint32_t hi[16], lo[16];
        #pragma unroll
        for (int i = 0; i < 16; i++) {
            float v0 = s[(nlg * 32 + 2*i) * 129 + w];
            float v1 = s[(nlg * 32 + 2*i + 1) * 129 + w];
            uint16_t h0 = bfbits(v0), h1 = bfbits(v1);
            uint16_t l0 = bfbits(v0 - bf2f(h0)), l1 = bfbits(v1 - bf2f(h1));
            hi[i] = (uint32_t)h0 | ((uint32_t)h1 << 16);
            lo[i] = (uint32_t)l0 | ((uint32_t)l1 << 16);
        }
        size_t gr = ((size_t)(nlbase + nlg) * 512) + wbase + w;
        char* dst = (char*)zT + gr * (ZTC * 2) + (p + 1) * 64;
        #pragma unroll
        for (int i = 0; i < 4; i++) {
            *(uint4*)(dst + i * 16)       = *(uint4*)(hi + i * 4);
            *(uint4*)(dst + 448 + i * 16) = *(uint4*)(lo + i * 4);
        }
    }
}

// ---------------------------------------------------------------- 6) W' = [hi(224)|lo(224)]
__global__ __launch_bounds__(256)
void build_W(const float* __restrict__ W, __nv_bfloat16* __restrict__ Wp) {
    int idx = blockIdx.x * 256 + threadIdx.x;      // 64*448
    if (idx >= COUT * ZTC) return;
    int o = idx / ZTC, k = idx % ZTC;
    float val = W[o * 224 + (k < 224 ? k : k - 224)];
    uint16_t hi = bfbits(val);
    uint16_t r  = (k < 224) ? hi : bfbits(val - bf2f(hi));
    ((uint16_t*)Wp)[idx] = r;
}

// ---------------------------------------------------------------- 7) mix GEMM (HMMA)
// tmp[(n,o,l), v] = bias[o] + zT[(n,l,v), :] (3-term schedule) @ W'
#define MIX_ASTG 3
#define MIX_APITCH 80                       // bytes per smem A row
#define MIX_ASTAGE (128 * MIX_APITCH)       // 10240 B
#define MIX_WP 456                          // smem W' pitch (bf16)
#define MIX_WBYTES (COUT * MIX_WP * 2)      // 58368 B
#define MIX_SMEM (MIX_WBYTES + 33792)       // 92160 (epilogue [64][132] fp32 fits)

__global__ __launch_bounds__(256, 2)
void mix_gemm(const __nv_bfloat16* __restrict__ zT, const __nv_bfloat16* __restrict__ Wp,
              const float* __restrict__ bias, float* __restrict__ tmp) {
    extern __shared__ char smem[];
    const uint32_t sb = smem_u32(smem);
    uint16_t* ws = (uint16_t*)smem;                        // [64][456]
    const uint32_t asb = sb + MIX_WBYTES;
    const int tid = threadIdx.x;
    const int wid = tid >> 5, lane = tid & 31;
    const int bm = blockIdx.x * 128;
    const int wm = wid & 3, wn = wid >> 2;

    // preload W' into smem (pitch 456)
    for (int i = tid; i < COUT * 224; i += 256) {          // u32 copies
        int o = i / 224, kk = (i % 224) * 2;
        *(uint32_t*)(ws + o * MIX_WP + kk) =
            *(const uint32_t*)((const uint16_t*)Wp + o * ZTC + kk);
    }

    float acc[2][4][4];
    #pragma unroll
    for (int i = 0; i < 2; i++)
        #pragma unroll
        for (int j = 0; j < 4; j++)
            #pragma unroll
            for (int q = 0; q < 4; q++) acc[i][j][q] = 0.f;

    auto load_stage = [&](int slot, int chunk) {
        const uint32_t base = asb + slot * MIX_ASTAGE;
        const int ac = acol_of(chunk);
        #pragma unroll
        for (int i = 0; i < 2; i++) {                      // 512 x 16B
            int c = tid + i * 256;
            int row = c >> 2, c16 = c & 3;
            cp_async16(base + row * MIX_APITCH + c16 * 16,
                       zT + ((size_t)bm + row) * ZTC + ac + c16 * 8);
        }
        asm volatile("cp.async.commit_group;" ::: "memory");
    };

    load_stage(0, 0);
    load_stage(1, 1);
    __syncthreads();    // also covers ws preload

    const int lrow = lane & 15;
    const int lkh  = (lane >> 4) << 3;
    const int og   = lane >> 2;            // 0..7 within n8
    const int kq   = (lane & 3) * 2;

    for (int it = 0; it < 21; it++) {
        if (it + 2 < 21) load_stage((it + 2) % MIX_ASTG, it + 2);
        int rem = 20 - it;
        if (rem >= 2)      asm volatile("cp.async.wait_group 2;" ::: "memory");
        else if (rem == 1) asm volatile("cp.async.wait_group 1;" ::: "memory");
        else               asm volatile("cp.async.wait_group 0;" ::: "memory");
        __syncthreads();

        const uint32_t abase = asb + (it % MIX_ASTG) * MIX_ASTAGE;
        const int bc = bcol_of(it);

        #pragma unroll
        for (int ks = 0; ks < 2; ks++) {
            uint32_t a_regs[2][4];
            #pragma unroll
            for (int mf = 0; mf < 2; mf++) {
                int row = wm * 32 + mf * 16 + lrow;
                ldsm4(a_regs[mf], abase + row * MIX_APITCH + (ks * 16 + lkh) * 2);
            }
            #pragma unroll
            for (int nq = 0; nq < 4; nq++) {
                int o = wn * 32 + nq * 8 + og;
                int k = bc + ks * 16 + kq;
                uint32_t b0 = *(uint32_t*)(ws + o * MIX_WP + k);
                uint32_t b1 = *(uint32_t*)(ws + o * MIX_WP + k + 8);
                #pragma unroll
                for (int mf = 0; mf < 2; mf++)
                    mma16816(acc[mf][nq], a_regs[mf], b0, b1);
            }
        }
        __syncthreads();
    }

    // ---- epilogue: stage [o][w] then coalesced tmp writes
    float* s2 = (float*)(smem + MIX_WBYTES);   // [64][132]
    const int gid = lane >> 2, tig = lane & 3;
    #pragma unroll
    for (int mf = 0; mf < 2; mf++) {
        int r0 = wm * 32 + mf * 16 + gid;
        #pragma unroll
        for (int nq = 0; nq < 4; nq++) {
            int o = wn * 32 + nq * 8 + tig * 2;
            float* d = acc[mf][nq];
            s2[o * 132 + r0] = d[0];       s2[(o + 1) * 132 + r0] = d[1];
            s2[o * 132 + r0 + 8] = d[2];   s2[(o + 1) * 132 + r0 + 8] = d[3];
        }
    }
    __syncthreads();

    const int nl = bm >> 9;                // one (n,l) per tile
    const int n = nl / 13, l = nl - n * 13;
    const int wbase = bm & 511;
    #pragma unroll
    for (int i = 0; i < 8; i++) {
        int idx = tid + i * 256;           // 2048 float4s
        int o = idx >> 5, q = idx & 31;
        float4 v = *(float4*)(s2 + o * 132 + q * 4);
        float bo = bias[o];
        v.x += bo; v.y += bo; v.z += bo; v.w += bo;
        *(float4*)(tmp + (((size_t)n * COUT + o) * L_ + l) * V_ + wbase + q * 4) = v;
    }
}

// ---------------------------------------------------------------- 8) tmp[n][o][l][v] -> out[n][o][v][l]
__global__ __launch_bounds__(256)
void out_transpose(const float* __restrict__ tmp, float* __restrict__ out) {
    __shared__ float s[V_ * L_];
    const int no  = blockIdx.x;
    const int tid = threadIdx.x;
    const float* src = tmp + (size_t)no * (V_ * L_);
    for (int i = tid; i < V_ * L_; i += 256) s[i] = src[i];
    __syncthreads();
    float* dst = out + (size_t)no * (V_ * L_);
    #pragma unroll
    for (int i = 0; i < 26; i++) {
        int addr = i * 256 + tid;          // contiguous store addr = v*13+l
        int v = addr / 13, l = addr - v * 13;
        dst[addr] = s[l * V_ + v];
    }
}

// ---------------------------------------------------------------- launcher
extern "C" void kernel_launch(void* const* d_in, const int* in_sizes, int n_in,
                              void* d_out, int out_size) {
    const float* x  = (const float*)d_in[0];
    const float* a0 = (const float*)d_in[1];
    const float* a1 = (const float*)d_in[2];
    const float* a2 = (const float*)d_in[3];
    const float* W  = (const float*)d_in[4];
    const float* b  = (const float*)d_in[5];
    float* out = (float*)d_out;

    float *pw, *tmp;
    __nv_bfloat16 *Abf, *Bbf, *zT, *Wp;
    cudaGetSymbolAddress((void**)&pw,  g_pow);
    cudaGetSymbolAddress((void**)&tmp, g_tmp);
    cudaGetSymbolAddress((void**)&Abf, g_Abf);
    cudaGetSymbolAddress((void**)&Bbf, g_Bbf);
    cudaGetSymbolAddress((void**)&zT,  g_zT);
    cudaGetSymbolAddress((void**)&Wp,  g_Wp);

    cudaFuncSetAttribute(mma_gemm, cudaFuncAttributeMaxDynamicSharedMemorySize, GEMM_SMEM);
    cudaFuncSetAttribute(mix_gemm, cudaFuncAttributeMaxDynamicSharedMemorySize, MIX_SMEM);
    cudaFuncSetAttribute(seed_zT,  cudaFuncAttributeMaxDynamicSharedMemorySize, 65536);

    pow_kernel<<<dim3(8, 8, 3), 256>>>(a0, a1, a2, pw);
    build_A<<<B_ * C_, 256>>>(x, Abf);
    build_B<<<(NB * 512) / 256, 256>>>(a0, a1, a2, pw, Bbf);
    seed_zT<<<B_ * L_, 256, 65536>>>(Abf, zT);
    build_W<<<(COUT * ZTC + 255) / 256, 256>>>(W, Wp);

    mma_gemm<<<dim3(M_ROWS / BMg, NB / BNg), 256, GEMM_SMEM>>>(Abf, Bbf, zT);

    mix_gemm<<<NLW / 128, 256, MIX_SMEM>>>(zT, Wp, b, tmp);
    out_transpose<<<B_ * COUT, 256>>>(tmp, out);
}

// round 7
// speedup vs baseline: 2.9328x; 1.3731x over previous
#include <cuda_runtime.h>
#include <cuda_fp16.h>
#include <cstdint>

// ---------------------------------------------------------------- constants
#define B_    64
#define C_    32
#define V_    512
#define L_    13
#define COUT  64
#define M_ROWS 26624            // B_*C_*L_  rows ordered (n,l,c)
#define NB    3072              // 6 support-powers * 512
#define KA    1024              // A' cols: [xh(512) | xl(512)]
#define KB    512               // B' cols: ah only
#define NLW   425984            // 832 (n,l) * 512 w
#define ZTC   448               // zT cols: [hi(224) | lo(224)]

// ---------------------------------------------------------------- scratch
__device__ __half g_Ah[(size_t)M_ROWS * KA];      // 54.5 MB
__device__ __half g_Bh[(size_t)NB * KB];          // 3.1 MB
__device__ __half g_zT[(size_t)NLW * ZTC];        // 381.7 MB
__device__ __half g_Wh[COUT * 224];
__device__ float  g_pow[3 * V_ * V_];
__device__ float  g_tmp[(size_t)B_ * COUT * L_ * V_];  // [n][o][l][v]

// ---------------------------------------------------------------- utils
__device__ __forceinline__ uint32_t smem_u32(const void* p) {
    uint32_t a;
    asm("{ .reg .u64 t; cvta.to.shared.u64 t, %1; cvt.u32.u64 %0, t; }" : "=r"(a) : "l"(p));
    return a;
}
__device__ __forceinline__ void cp_async16(uint32_t s, const void* g) {
    asm volatile("cp.async.cg.shared.global [%0], [%1], 16;" :: "r"(s), "l"(g));
}
__device__ __forceinline__ void ldsm4(uint32_t* r, uint32_t addr) {
    asm volatile("ldmatrix.sync.aligned.m8n8.x4.shared.b16 {%0,%1,%2,%3}, [%4];"
                 : "=r"(r[0]), "=r"(r[1]), "=r"(r[2]), "=r"(r[3]) : "r"(addr));
}
__device__ __forceinline__ void mma16816(float* d, const uint32_t* a, uint32_t b0, uint32_t b1) {
    asm volatile(
        "mma.sync.aligned.m16n8k16.row.col.f32.f16.f16.f32 "
        "{%0,%1,%2,%3}, {%4,%5,%6,%7}, {%8,%9}, {%0,%1,%2,%3};"
        : "+f"(d[0]), "+f"(d[1]), "+f"(d[2]), "+f"(d[3])
        : "r"(a[0]), "r"(a[1]), "r"(a[2]), "r"(a[3]), "r"(b0), "r"(b1));
}
#define SW128(off) ((off) ^ (((off) >> 3) & 0x70))

__device__ __forceinline__ uint16_t hbits(float f) {
    __half h = __float2half_rn(f);
    return *reinterpret_cast<uint16_t*>(&h);
}
__device__ __forceinline__ float h2f(uint16_t u) {
    __half h = *reinterpret_cast<__half*>(&u);
    return __half2float(h);
}

// ---------------------------------------------------------------- 1) a^2 (fp32)
__global__ __launch_bounds__(256)
void pow_kernel(const float* __restrict__ a0, const float* __restrict__ a1,
                const float* __restrict__ a2, float* __restrict__ out) {
    const float* A = (blockIdx.z == 0) ? a0 : (blockIdx.z == 1 ? a1 : a2);
    float* Cc = out + (size_t)blockIdx.z * V_ * V_;
    __shared__ float As[16][64];
    __shared__ float Bs[16][68];
    const int tid = threadIdx.x;
    const int bm = blockIdx.y * 64, bn = blockIdx.x * 64;
    const int tx = tid & 15, ty = tid >> 4;
    float acc[4][4] = {};
    for (int kb = 0; kb < 512; kb += 16) {
        float4 va = *(const float4*)(A + (size_t)(bm + (tid >> 2)) * 512 + kb + (tid & 3) * 4);
        As[(tid & 3) * 4 + 0][tid >> 2] = va.x;
        As[(tid & 3) * 4 + 1][tid >> 2] = va.y;
        As[(tid & 3) * 4 + 2][tid >> 2] = va.z;
        As[(tid & 3) * 4 + 3][tid >> 2] = va.w;
        *(float4*)&Bs[tid >> 4][(tid & 15) * 4] =
            *(const float4*)(A + (size_t)(kb + (tid >> 4)) * 512 + bn + (tid & 15) * 4);
        __syncthreads();
        #pragma unroll
        for (int k = 0; k < 16; k++) {
            float wf[4], hf[4];
            #pragma unroll
            for (int i = 0; i < 4; i++) wf[i] = As[k][ty * 4 + i];
            #pragma unroll
            for (int j = 0; j < 4; j++) hf[j] = Bs[k][tx * 4 + j];
            #pragma unroll
            for (int i = 0; i < 4; i++)
                #pragma unroll
                for (int j = 0; j < 4; j++) acc[i][j] = fmaf(wf[i], hf[j], acc[i][j]);
        }
        __syncthreads();
    }
    #pragma unroll
    for (int i = 0; i < 4; i++)
        #pragma unroll
        for (int j = 0; j < 4; j++)
            Cc[(size_t)(bm + ty * 4 + i) * 512 + bn + tx * 4 + j] = acc[i][j];
}

// ---------------------------------------------------------------- 2) A' rows (n,l,c): [xh|xl]
__global__ __launch_bounds__(256)
void build_A(const float* __restrict__ x, __half* __restrict__ Ah) {
    __shared__ float s[V_ * L_];
    const int nc = blockIdx.x;              // n*32 + c
    const int n = nc >> 5, c = nc & 31;
    const int tid = threadIdx.x;
    const float* slab = x + (size_t)nc * (V_ * L_);
    for (int i = tid; i < V_ * L_; i += 256) s[i] = slab[i];
    __syncthreads();
    for (int e = tid; e < V_ * L_; e += 256) {
        int l = e >> 9, v = e & 511;
        float val = s[v * L_ + l];
        size_t m = ((size_t)n * L_ + l) * 32 + c;
        uint16_t hi = hbits(val);
        uint16_t lo = hbits(val - h2f(hi));
        uint16_t* ar = (uint16_t*)(Ah + m * KA);
        ar[v] = hi; ar[512 + v] = lo;
    }
}

// ---------------------------------------------------------------- 3) B' (hi only)
__global__ __launch_bounds__(256)
void build_B(const float* __restrict__ a0, const float* __restrict__ a1,
             const float* __restrict__ a2, const float* __restrict__ pw,
             __half* __restrict__ Bh) {
    int idx = blockIdx.x * 256 + threadIdx.x;
    if (idx >= NB * 512) return;
    int v = idx & 511;
    int j = idx >> 9;                // B' row: p*512 + w
    int p = j >> 9;
    int w = j & 511;
    const float* P = (p & 1) ? (pw + (size_t)(p >> 1) * V_ * V_)
                             : (p == 0 ? a0 : (p == 2 ? a1 : a2));
    ((uint16_t*)Bh)[(size_t)j * KB + v] = hbits(P[(size_t)v * 512 + w]);
}

// ---------------------------------------------------------------- 4) seed zT block 0 (x itself)
__global__ __launch_bounds__(256)
void seed_zT(const __half* __restrict__ Ah, __half* __restrict__ zT) {
    extern __shared__ uint32_t s32[];       // [32][513] u32 (pitch odd -> conflict-free)
    uint16_t* s16 = (uint16_t*)s32;
    const int nl = blockIdx.x;
    const int tid = threadIdx.x;
    for (int i = tid; i < 32 * 512; i += 256) {
        int c = i >> 9, kk = i & 511;
        const uint32_t* pa = (const uint32_t*)(Ah + ((size_t)nl * 32 + c) * KA);
        s32[c * 513 + kk] = pa[kk];
    }
    __syncthreads();
    #pragma unroll
    for (int rep = 0; rep < 2; rep++) {
        int v = tid + rep * 256;
        uint32_t hi[16], lo[16];
        #pragma unroll
        for (int i = 0; i < 16; i++) {
            uint32_t h0 = s16[(2*i) * 1026 + v],       h1 = s16[(2*i+1) * 1026 + v];
            uint32_t l0 = s16[(2*i) * 1026 + 512 + v], l1 = s16[(2*i+1) * 1026 + 512 + v];
            hi[i] = h0 | (h1 << 16);
            lo[i] = l0 | (l1 << 16);
        }
        char* dst = (char*)zT + ((size_t)nl * 512 + v) * (ZTC * 2);
        #pragma unroll
        for (int i = 0; i < 4; i++) {
            *(uint4*)(dst + i * 16)       = *(uint4*)(hi + i * 4);
            *(uint4*)(dst + 448 + i * 16) = *(uint4*)(lo + i * 4);
        }
    }
}

// ---------------------------------------------------------------- 5) GEMM1 (HMMA fp16)
#define BMg 128
#define BNg 128
#define BKg 64
#define NSTG 3
#define STG_A (BMg * BKg * 2)
#define STG_B (BNg * BKg * 2)
#define STG_BYTES (STG_A + STG_B)          // 32768
#define GEMM_SMEM (NSTG * STG_BYTES)       // 98304
#define KITERS 16                           // KA/BKg; B repeats (it&7)

__global__ __launch_bounds__(256, 2)
void mma_gemm(const __half* __restrict__ A, const __half* __restrict__ Bm,
              __half* __restrict__ zT) {
    extern __shared__ char smem[];
    const uint32_t sb = smem_u32(smem);
    const int tid = threadIdx.x;
    const int wid = tid >> 5, lane = tid & 31;
    const int bm = blockIdx.y * BMg;       // M on y -> N-fastest launch for A L2 reuse
    const int bn = blockIdx.x * BNg;
    const int wm = wid & 3;
    const int wn = wid >> 2;

    float acc[2][8][4];
    #pragma unroll
    for (int i = 0; i < 2; i++)
        #pragma unroll
        for (int j = 0; j < 8; j++)
            #pragma unroll
            for (int q = 0; q < 4; q++) acc[i][j][q] = 0.f;

    auto load_stage = [&](int slot, int it) {
        const uint32_t abase = sb + slot * STG_BYTES;
        const uint32_t bbase = abase + STG_A;
        const __half* Ag = A + (size_t)bm * KA + it * BKg;
        const __half* Bg = Bm + (size_t)bn * KB + (it & 7) * BKg;
        #pragma unroll
        for (int i = 0; i < 4; i++) {
            int c = tid + i * 256;
            int row = c >> 3, c16 = c & 7;
            uint32_t off = (uint32_t)(row * 128 + c16 * 16);
            cp_async16(abase + SW128(off), Ag + (size_t)row * KA + c16 * 8);
        }
        #pragma unroll
        for (int i = 0; i < 4; i++) {
            int c = tid + i * 256;
            int row = c >> 3, c16 = c & 7;
            uint32_t off = (uint32_t)(row * 128 + c16 * 16);
            cp_async16(bbase + SW128(off), Bg + (size_t)row * KB + c16 * 8);
        }
        asm volatile("cp.async.commit_group;" ::: "memory");
    };

    load_stage(0, 0);
    load_stage(1, 1);

    for (int it = 0; it < KITERS; it++) {
        if (it + 2 < KITERS) load_stage((it + 2) % NSTG, it + 2);
        int rem = KITERS - 1 - it;
        if (rem >= 2)      asm volatile("cp.async.wait_group 2;" ::: "memory");
        else if (rem == 1) asm volatile("cp.async.wait_group 1;" ::: "memory");
        else               asm volatile("cp.async.wait_group 0;" ::: "memory");
        __syncthreads();

        const uint32_t abase = sb + (it % NSTG) * STG_BYTES;
        const uint32_t bbase = abase + STG_A;
        const int lrow = lane & 15;
        const int lkh  = (lane >> 4) << 3;

        #pragma unroll
        for (int ks = 0; ks < 4; ks++) {
            const int k0 = ks * 16;
            uint32_t a_regs[2][4];
            #pragma unroll
            for (int mf = 0; mf < 2; mf++) {
                int row = wm * 32 + mf * 16 + lrow;
                ldsm4(a_regs[mf], abase + SW128((uint32_t)(row * 128 + (k0 + lkh) * 2)));
            }
            uint32_t b_regs[4][4];
            #pragma unroll
            for (int nq = 0; nq < 4; nq++) {
                int row = wn * 64 + nq * 16 + lrow;
                ldsm4(b_regs[nq], bbase + SW128((uint32_t)(row * 128 + (k0 + lkh) * 2)));
            }
            #pragma unroll
            for (int mf = 0; mf < 2; mf++)
                #pragma unroll
                for (int nq = 0; nq < 4; nq++) {
                    mma16816(acc[mf][nq * 2 + 0], a_regs[mf], b_regs[nq][0], b_regs[nq][2]);
                    mma16816(acc[mf][nq * 2 + 1], a_regs[mf], b_regs[nq][1], b_regs[nq][3]);
                }
        }
        __syncthreads();
    }

    // epilogue: acc -> smem fp32 [128][129] -> zT fp16 hi/lo, c-transposed
    float* s = (float*)smem;
    const int gid = lane >> 2, tig = lane & 3;
    #pragma unroll
    for (int mf = 0; mf < 2; mf++) {
        int r0 = wm * 32 + mf * 16 + gid;
        #pragma unroll
        for (int nf = 0; nf < 8; nf++) {
            int cc = wn * 64 + nf * 8 + tig * 2;
            float* d = acc[mf][nf];
            s[r0 * 129 + cc] = d[0];       s[r0 * 129 + cc + 1] = d[1];
            s[(r0 + 8) * 129 + cc] = d[2]; s[(r0 + 8) * 129 + cc + 1] = d[3];
        }
    }
    __syncthreads();

    const int p = bn >> 9;
    const int wbase = bn & 511;
    const int nlbase = bm >> 5;
    #pragma unroll
    for (int rep = 0; rep < 2; rep++) {
        int rw = tid + rep * 256;
        int nlg = rw >> 7, w = rw & 127;
        uint32_t hi[16], lo[16];
        #pragma unroll
        for (int i = 0; i < 16; i++) {
            float v0 = s[(nlg * 32 + 2*i) * 129 + w];
            float v1 = s[(nlg * 32 + 2*i + 1) * 129 + w];
            uint16_t h0 = hbits(v0), h1 = hbits(v1);
            uint16_t l0 = hbits(v0 - h2f(h0)), l1 = hbits(v1 - h2f(h1));
            hi[i] = (uint32_t)h0 | ((uint32_t)h1 << 16);
            lo[i] = (uint32_t)l0 | ((uint32_t)l1 << 16);
        }
        size_t gr = ((size_t)(nlbase + nlg) * 512) + wbase + w;
        char* dst = (char*)zT + gr * (ZTC * 2) + (p + 1) * 64;
        #pragma unroll
        for (int i = 0; i < 4; i++) {
            *(uint4*)(dst + i * 16)       = *(uint4*)(hi + i * 4);
            *(uint4*)(dst + 448 + i * 16) = *(uint4*)(lo + i * 4);
        }
    }
}

// ---------------------------------------------------------------- 6) W fp32 -> fp16
__global__ __launch_bounds__(256)
void build_W(const float* __restrict__ W, __half* __restrict__ Wh) {
    int idx = blockIdx.x * 256 + threadIdx.x;
    if (idx >= COUT * 224) return;
    ((uint16_t*)Wh)[idx] = hbits(W[idx]);
}

// ---------------------------------------------------------------- 7) mix GEMM (HMMA fp16)
// tmp[(n,o,l), v] = bias[o] + zT[(n,l,v), :] @ Wh (14-chunk 2-term schedule)
#define MIX_WP 232                          // ws pitch (u16)
#define MIX_WBYTES (COUT * MIX_WP * 2)      // 29696
#define MIX_APITCH 80
#define MIX_ASTAGE (128 * MIX_APITCH)       // 10240
#define MIX_SMEM (MIX_WBYTES + 33792)       // 63488 (epilogue [64][132] fp32 after ws)

__global__ __launch_bounds__(256, 2)
void mix_gemm(const __half* __restrict__ zT, const __half* __restrict__ Wh,
              const float* __restrict__ bias, float* __restrict__ tmp) {
    extern __shared__ char smem[];
    const uint32_t sb = smem_u32(smem);
    uint16_t* ws = (uint16_t*)smem;                        // [64][232]
    const uint32_t asb = sb + MIX_WBYTES;
    const int tid = threadIdx.x;
    const int wid = tid >> 5, lane = tid & 31;
    const int bm = blockIdx.x * 128;
    const int wm = wid & 3, wn = wid >> 2;

    for (int i = tid; i < COUT * 112; i += 256) {          // u32 copies of 224 cols
        int o = i / 112, kk = (i % 112) * 2;
        *(uint32_t*)(ws + o * MIX_WP + kk) =
            *(const uint32_t*)((const uint16_t*)Wh + o * 224 + kk);
    }

    float acc[2][4][4];
    #pragma unroll
    for (int i = 0; i < 2; i++)
        #pragma unroll
        for (int j = 0; j < 4; j++)
            #pragma unroll
            for (int q = 0; q < 4; q++) acc[i][j][q] = 0.f;

    auto load_stage = [&](int slot, int chunk) {
        const uint32_t base = asb + slot * MIX_ASTAGE;
        const int ac = chunk * 32;                         // contiguous hi(0..223)|lo(224..447)
        #pragma unroll
        for (int i = 0; i < 2; i++) {
            int c = tid + i * 256;
            int row = c >> 2, c16 = c & 3;
            cp_async16(base + row * MIX_APITCH + c16 * 16,
                       zT + ((size_t)bm + row) * ZTC + ac + c16 * 8);
        }
        asm volatile("cp.async.commit_group;" ::: "memory");
    };

    load_stage(0, 0);
    load_stage(1, 1);
    __syncthreads();

    const int lrow = lane & 15;
    const int lkh  = (lane >> 4) << 3;
    const int og   = lane >> 2;
    const int kq   = (lane & 3) * 2;

    for (int it = 0; it < 14; it++) {
        if (it + 2 < 14) load_stage((it + 2) % 3, it + 2);
        int rem = 13 - it;
        if (rem >= 2)      asm volatile("cp.async.wait_group 2;" ::: "memory");
        else if (rem == 1) asm volatile("cp.async.wait_group 1;" ::: "memory");
        else               asm volatile("cp.async.wait_group 0;" ::: "memory");
        __syncthreads();

        const uint32_t abase = asb + (it % 3) * MIX_ASTAGE;
        const int bc = (it < 7) ? it * 32 : (it - 7) * 32;

        #pragma unroll
        for (int ks = 0; ks < 2; ks++) {
            uint32_t a_regs[2][4];
            #pragma unroll
            for (int mf = 0; mf < 2; mf++) {
                int row = wm * 32 + mf * 16 + lrow;
                ldsm4(a_regs[mf], abase + row * MIX_APITCH + (ks * 16 + lkh) * 2);
            }
            #pragma unroll
            for (int nq = 0; nq < 4; nq++) {
                int o = wn * 32 + nq * 8 + og;
                int k = bc + ks * 16 + kq;
                uint32_t b0 = *(uint32_t*)(ws + o * MIX_WP + k);
                uint32_t b1 = *(uint32_t*)(ws + o * MIX_WP + k + 8);
                #pragma unroll
                for (int mf = 0; mf < 2; mf++)
                    mma16816(acc[mf][nq], a_regs[mf], b0, b1);
            }
        }
        __syncthreads();
    }

    // epilogue: stage [o][w] (pitch 132) then coalesced tmp writes
    float* s2 = (float*)(smem + MIX_WBYTES);
    const int gid = lane >> 2, tig = lane & 3;
    #pragma unroll
    for (int mf = 0; mf < 2; mf++) {
        int r0 = wm * 32 + mf * 16 + gid;
        #pragma unroll
        for (int nq = 0; nq < 4; nq++) {
            int o = wn * 32 + nq * 8 + tig * 2;
            float* d = acc[mf][nq];
            s2[o * 132 + r0] = d[0];       s2[(o + 1) * 132 + r0] = d[1];
            s2[o * 132 + r0 + 8] = d[2];   s2[(o + 1) * 132 + r0 + 8] = d[3];
        }
    }
    __syncthreads();

    const int nl = bm >> 9;
    const int n = nl / 13, l = nl - n * 13;
    const int wbase = bm & 511;
    #pragma unroll
    for (int i = 0; i < 8; i++) {
        int idx = tid + i * 256;
        int o = idx >> 5, q = idx & 31;
        float4 v = *(float4*)(s2 + o * 132 + q * 4);
        float bo = bias[o];
        v.x += bo; v.y += bo; v.z += bo; v.w += bo;
        *(float4*)(tmp + (((size_t)n * COUT + o) * L_ + l) * V_ + wbase + q * 4) = v;
    }
}

// ---------------------------------------------------------------- 8) tmp[n][o][l][v] -> out[n][o][v][l]
__global__ __launch_bounds__(256)
void out_transpose(const float* __restrict__ tmp, float* __restrict__ out) {
    __shared__ float s[13 * 520];
    const int no  = blockIdx.x;
    const int tid = threadIdx.x;
    const float* src = tmp + (size_t)no * (V_ * L_);
    for (int i = tid; i < V_ * L_; i += 256)
        s[(i >> 9) * 520 + (i & 511)] = src[i];
    __syncthreads();
    float* dst = out + (size_t)no * (V_ * L_);
    #pragma unroll
    for (int i = 0; i < 26; i++) {
        int addr = i * 256 + tid;          // contiguous store addr = v*13+l
        int v = addr / 13, l = addr - v * 13;
        dst[addr] = s[l * 520 + v];
    }
}

// ---------------------------------------------------------------- launcher
extern "C" void kernel_launch(void* const* d_in, const int* in_sizes, int n_in,
                              void* d_out, int out_size) {
    const float* x  = (const float*)d_in[0];
    const float* a0 = (const float*)d_in[1];
    const float* a1 = (const float*)d_in[2];
    const float* a2 = (const float*)d_in[3];
    const float* W  = (const float*)d_in[4];
    const float* b  = (const float*)d_in[5];
    float* out = (float*)d_out;

    float *pw, *tmp;
    __half *Ah, *Bh, *zT, *Wh;
    cudaGetSymbolAddress((void**)&pw,  g_pow);
    cudaGetSymbolAddress((void**)&tmp, g_tmp);
    cudaGetSymbolAddress((void**)&Ah,  g_Ah);
    cudaGetSymbolAddress((void**)&Bh,  g_Bh);
    cudaGetSymbolAddress((void**)&zT,  g_zT);
    cudaGetSymbolAddress((void**)&Wh,  g_Wh);

    cudaFuncSetAttribute(mma_gemm, cudaFuncAttributeMaxDynamicSharedMemorySize, GEMM_SMEM);
    cudaFuncSetAttribute(mix_gemm, cudaFuncAttributeMaxDynamicSharedMemorySize, MIX_SMEM);
    cudaFuncSetAttribute(seed_zT,  cudaFuncAttributeMaxDynamicSharedMemorySize, 32 * 513 * 4);

    pow_kernel<<<dim3(8, 8, 3), 256>>>(a0, a1, a2, pw);
    build_A<<<B_ * C_, 256>>>(x, Ah);
    build_B<<<(NB * 512) / 256, 256>>>(a0, a1, a2, pw, Bh);
    seed_zT<<<B_ * L_, 256, 32 * 513 * 4>>>(Ah, zT);
    build_W<<<(COUT * 224 + 255) / 256, 256>>>(W, Wh);

    mma_gemm<<<dim3(NB / BNg, M_ROWS / BMg), 256, GEMM_SMEM>>>(Ah, Bh, zT);

    mix_gemm<<<NLW / 128, 256, MIX_SMEM>>>(zT, Wh, b, tmp);
    out_transpose<<<B_ * COUT, 256>>>(tmp, out);
}

// round 8
// speedup vs baseline: 3.5298x; 1.2036x over previous
#include <cuda_runtime.h>
#include <cuda_fp16.h>
#include <cstdint>

// ---------------------------------------------------------------- constants
#define B_    64
#define C_    32
#define V_    512
#define L_    13
#define COUT  64
#define M_ROWS 26624            // B_*C_*L_  rows ordered (n,l,c)
#define NB    3072              // 6 support-powers * 512
#define KA    1024              // A' cols: [xh(512) | xl(512)]
#define KB    512               // B' cols: ah only
#define NLW   425984            // 832 (n,l) * 512 w
#define ZTC   224               // zT cols: hi only (7 chan blocks x 32)

// ---------------------------------------------------------------- scratch
__device__ __half g_Ah[(size_t)M_ROWS * KA];      // 54.5 MB
__device__ __half g_Bh[(size_t)NB * KB];          // 3.1 MB
__device__ __half g_zT[(size_t)NLW * ZTC];        // 190.8 MB
__device__ __half g_Wh[COUT * 224];
__device__ float  g_pow[3 * V_ * V_];
__device__ float  g_tmp[(size_t)B_ * COUT * L_ * V_];  // [n][o][l][v]

// ---------------------------------------------------------------- utils
__device__ __forceinline__ uint32_t smem_u32(const void* p) {
    uint32_t a;
    asm("{ .reg .u64 t; cvta.to.shared.u64 t, %1; cvt.u32.u64 %0, t; }" : "=r"(a) : "l"(p));
    return a;
}
__device__ __forceinline__ void cp_async16(uint32_t s, const void* g) {
    asm volatile("cp.async.cg.shared.global [%0], [%1], 16;" :: "r"(s), "l"(g));
}
__device__ __forceinline__ void ldsm4(uint32_t* r, uint32_t addr) {
    asm volatile("ldmatrix.sync.aligned.m8n8.x4.shared.b16 {%0,%1,%2,%3}, [%4];"
                 : "=r"(r[0]), "=r"(r[1]), "=r"(r[2]), "=r"(r[3]) : "r"(addr));
}
__device__ __forceinline__ void mma16816(float* d, const uint32_t* a, uint32_t b0, uint32_t b1) {
    asm volatile(
        "mma.sync.aligned.m16n8k16.row.col.f32.f16.f16.f32 "
        "{%0,%1,%2,%3}, {%4,%5,%6,%7}, {%8,%9}, {%0,%1,%2,%3};"
        : "+f"(d[0]), "+f"(d[1]), "+f"(d[2]), "+f"(d[3])
        : "r"(a[0]), "r"(a[1]), "r"(a[2]), "r"(a[3]), "r"(b0), "r"(b1));
}
#define SW128(off) ((off) ^ (((off) >> 3) & 0x70))

__device__ __forceinline__ uint16_t hbits(float f) {
    __half h = __float2half_rn(f);
    return *reinterpret_cast<uint16_t*>(&h);
}
__device__ __forceinline__ float h2f(uint16_t u) {
    __half h = *reinterpret_cast<__half*>(&u);
    return __half2float(h);
}

// ---------------------------------------------------------------- 1) a^2 (fp32)
__global__ __launch_bounds__(256)
void pow_kernel(const float* __restrict__ a0, const float* __restrict__ a1,
                const float* __restrict__ a2, float* __restrict__ out) {
    const float* A = (blockIdx.z == 0) ? a0 : (blockIdx.z == 1 ? a1 : a2);
    float* Cc = out + (size_t)blockIdx.z * V_ * V_;
    __shared__ float As[16][64];
    __shared__ float Bs[16][68];
    const int tid = threadIdx.x;
    const int bm = blockIdx.y * 64, bn = blockIdx.x * 64;
    const int tx = tid & 15, ty = tid >> 4;
    float acc[4][4] = {};
    for (int kb = 0; kb < 512; kb += 16) {
        float4 va = *(const float4*)(A + (size_t)(bm + (tid >> 2)) * 512 + kb + (tid & 3) * 4);
        As[(tid & 3) * 4 + 0][tid >> 2] = va.x;
        As[(tid & 3) * 4 + 1][tid >> 2] = va.y;
        As[(tid & 3) * 4 + 2][tid >> 2] = va.z;
        As[(tid & 3) * 4 + 3][tid >> 2] = va.w;
        *(float4*)&Bs[tid >> 4][(tid & 15) * 4] =
            *(const float4*)(A + (size_t)(kb + (tid >> 4)) * 512 + bn + (tid & 15) * 4);
        __syncthreads();
        #pragma unroll
        for (int k = 0; k < 16; k++) {
            float wf[4], hf[4];
            #pragma unroll
            for (int i = 0; i < 4; i++) wf[i] = As[k][ty * 4 + i];
            #pragma unroll
            for (int j = 0; j < 4; j++) hf[j] = Bs[k][tx * 4 + j];
            #pragma unroll
            for (int i = 0; i < 4; i++)
                #pragma unroll
                for (int j = 0; j < 4; j++) acc[i][j] = fmaf(wf[i], hf[j], acc[i][j]);
        }
        __syncthreads();
    }
    #pragma unroll
    for (int i = 0; i < 4; i++)
        #pragma unroll
        for (int j = 0; j < 4; j++)
            Cc[(size_t)(bm + ty * 4 + i) * 512 + bn + tx * 4 + j] = acc[i][j];
}

// ---------------------------------------------------------------- 2) A' rows (n,l,c): [xh|xl]
__global__ __launch_bounds__(256)
void build_A(const float* __restrict__ x, __half* __restrict__ Ah) {
    __shared__ float s[V_ * L_];
    const int nc = blockIdx.x;              // n*32 + c
    const int n = nc >> 5, c = nc & 31;
    const int tid = threadIdx.x;
    const float* slab = x + (size_t)nc * (V_ * L_);
    for (int i = tid; i < V_ * L_; i += 256) s[i] = slab[i];
    __syncthreads();
    for (int e = tid; e < V_ * L_; e += 256) {
        int l = e >> 9, v = e & 511;
        float val = s[v * L_ + l];
        size_t m = ((size_t)n * L_ + l) * 32 + c;
        uint16_t hi = hbits(val);
        uint16_t lo = hbits(val - h2f(hi));
        uint16_t* ar = (uint16_t*)(Ah + m * KA);
        ar[v] = hi; ar[512 + v] = lo;
    }
}

// ---------------------------------------------------------------- 3) B' (hi only)
__global__ __launch_bounds__(256)
void build_B(const float* __restrict__ a0, const float* __restrict__ a1,
             const float* __restrict__ a2, const float* __restrict__ pw,
             __half* __restrict__ Bh) {
    int idx = blockIdx.x * 256 + threadIdx.x;
    if (idx >= NB * 512) return;
    int v = idx & 511;
    int j = idx >> 9;                // B' row: p*512 + w
    int p = j >> 9;
    int w = j & 511;
    const float* P = (p & 1) ? (pw + (size_t)(p >> 1) * V_ * V_)
                             : (p == 0 ? a0 : (p == 2 ? a1 : a2));
    ((uint16_t*)Bh)[(size_t)j * KB + v] = hbits(P[(size_t)v * 512 + w]);
}

// ---------------------------------------------------------------- 4) seed zT block 0 (x hi)
__global__ __launch_bounds__(512)
void seed_zT(const __half* __restrict__ Ah, __half* __restrict__ zT) {
    __shared__ uint32_t s32[32 * 257];      // [c][256 u32 of hi], pitch 257
    uint16_t* s16 = (uint16_t*)s32;
    const int nl = blockIdx.x;
    const int tid = threadIdx.x;
    for (int i = tid; i < 32 * 256; i += 512) {
        int c = i >> 8, kk = i & 255;
        const uint32_t* pa = (const uint32_t*)(Ah + ((size_t)nl * 32 + c) * KA);
        s32[c * 257 + kk] = pa[kk];
    }
    __syncthreads();
    const int v = tid;                      // 512 threads = 512 v
    uint32_t hi[16];
    #pragma unroll
    for (int i = 0; i < 16; i++) {
        uint32_t w0 = s32[(2*i) * 257 + (v >> 1)];
        uint32_t w1 = s32[(2*i+1) * 257 + (v >> 1)];
        uint16_t h0 = (v & 1) ? (uint16_t)(w0 >> 16) : (uint16_t)w0;
        uint16_t h1 = (v & 1) ? (uint16_t)(w1 >> 16) : (uint16_t)w1;
        hi[i] = (uint32_t)h0 | ((uint32_t)h1 << 16);
    }
    char* dst = (char*)zT + ((size_t)nl * 512 + v) * (ZTC * 2);
    #pragma unroll
    for (int i = 0; i < 4; i++)
        *(uint4*)(dst + i * 16) = *(uint4*)(hi + i * 4);
    (void)s16;
}

// ---------------------------------------------------------------- 5) GEMM1 (HMMA fp16)
#define BMg 128
#define BNg 128
#define BKg 64
#define NSTG 3
#define STG_A (BMg * BKg * 2)
#define STG_B (BNg * BKg * 2)
#define STG_BYTES (STG_A + STG_B)          // 32768
#define GEMM_SMEM (NSTG * STG_BYTES)       // 98304
#define KITERS 16                           // KA/BKg; B repeats (it&7)

__global__ __launch_bounds__(256, 2)
void mma_gemm(const __half* __restrict__ A, const __half* __restrict__ Bm,
              __half* __restrict__ zT) {
    extern __shared__ char smem[];
    const uint32_t sb = smem_u32(smem);
    const int tid = threadIdx.x;
    const int wid = tid >> 5, lane = tid & 31;
    const int bm = blockIdx.y * BMg;       // N-fastest launch for A L2 reuse
    const int bn = blockIdx.x * BNg;
    const int wm = wid & 3;
    const int wn = wid >> 2;

    float acc[2][8][4];
    #pragma unroll
    for (int i = 0; i < 2; i++)
        #pragma unroll
        for (int j = 0; j < 8; j++)
            #pragma unroll
            for (int q = 0; q < 4; q++) acc[i][j][q] = 0.f;

    auto load_stage = [&](int slot, int it) {
        const uint32_t abase = sb + slot * STG_BYTES;
        const uint32_t bbase = abase + STG_A;
        const __half* Ag = A + (size_t)bm * KA + it * BKg;
        const __half* Bg = Bm + (size_t)bn * KB + (it & 7) * BKg;
        #pragma unroll
        for (int i = 0; i < 4; i++) {
            int c = tid + i * 256;
            int row = c >> 3, c16 = c & 7;
            uint32_t off = (uint32_t)(row * 128 + c16 * 16);
            cp_async16(abase + SW128(off), Ag + (size_t)row * KA + c16 * 8);
        }
        #pragma unroll
        for (int i = 0; i < 4; i++) {
            int c = tid + i * 256;
            int row = c >> 3, c16 = c & 7;
            uint32_t off = (uint32_t)(row * 128 + c16 * 16);
            cp_async16(bbase + SW128(off), Bg + (size_t)row * KB + c16 * 8);
        }
        asm volatile("cp.async.commit_group;" ::: "memory");
    };

    load_stage(0, 0);
    load_stage(1, 1);

    for (int it = 0; it < KITERS; it++) {
        if (it + 2 < KITERS) load_stage((it + 2) % NSTG, it + 2);
        int rem = KITERS - 1 - it;
        if (rem >= 2)      asm volatile("cp.async.wait_group 2;" ::: "memory");
        else if (rem == 1) asm volatile("cp.async.wait_group 1;" ::: "memory");
        else               asm volatile("cp.async.wait_group 0;" ::: "memory");
        __syncthreads();

        const uint32_t abase = sb + (it % NSTG) * STG_BYTES;
        const uint32_t bbase = abase + STG_A;
        const int lrow = lane & 15;
        const int lkh  = (lane >> 4) << 3;

        #pragma unroll
        for (int ks = 0; ks < 4; ks++) {
            const int k0 = ks * 16;
            uint32_t a_regs[2][4];
            #pragma unroll
            for (int mf = 0; mf < 2; mf++) {
                int row = wm * 32 + mf * 16 + lrow;
                ldsm4(a_regs[mf], abase + SW128((uint32_t)(row * 128 + (k0 + lkh) * 2)));
            }
            uint32_t b_regs[4][4];
            #pragma unroll
            for (int nq = 0; nq < 4; nq++) {
                int row = wn * 64 + nq * 16 + lrow;
                ldsm4(b_regs[nq], bbase + SW128((uint32_t)(row * 128 + (k0 + lkh) * 2)));
            }
            #pragma unroll
            for (int mf = 0; mf < 2; mf++)
                #pragma unroll
                for (int nq = 0; nq < 4; nq++) {
                    mma16816(acc[mf][nq * 2 + 0], a_regs[mf], b_regs[nq][0], b_regs[nq][2]);
                    mma16816(acc[mf][nq * 2 + 1], a_regs[mf], b_regs[nq][1], b_regs[nq][3]);
                }
        }
        __syncthreads();
    }

    // epilogue: acc -> smem fp32 [128][129] -> zT fp16 hi, c-transposed
    float* s = (float*)smem;
    const int gid = lane >> 2, tig = lane & 3;
    #pragma unroll
    for (int mf = 0; mf < 2; mf++) {
        int r0 = wm * 32 + mf * 16 + gid;
        #pragma unroll
        for (int nf = 0; nf < 8; nf++) {
            int cc = wn * 64 + nf * 8 + tig * 2;
            float* d = acc[mf][nf];
            s[r0 * 129 + cc] = d[0];       s[r0 * 129 + cc + 1] = d[1];
            s[(r0 + 8) * 129 + cc] = d[2]; s[(r0 + 8) * 129 + cc + 1] = d[3];
        }
    }
    __syncthreads();

    const int p = bn >> 9;
    const int wbase = bn & 511;
    const int nlbase = bm >> 5;
    #pragma unroll
    for (int rep = 0; rep < 2; rep++) {
        int rw = tid + rep * 256;
        int nlg = rw >> 7, w = rw & 127;
        uint32_t hi[16];
        #pragma unroll
        for (int i = 0; i < 16; i++) {
            float v0 = s[(nlg * 32 + 2*i) * 129 + w];
            float v1 = s[(nlg * 32 + 2*i + 1) * 129 + w];
            hi[i] = (uint32_t)hbits(v0) | ((uint32_t)hbits(v1) << 16);
        }
        size_t gr = ((size_t)(nlbase + nlg) * 512) + wbase + w;
        char* dst = (char*)zT + gr * (ZTC * 2) + (p + 1) * 64;
        #pragma unroll
        for (int i = 0; i < 4; i++)
            *(uint4*)(dst + i * 16) = *(uint4*)(hi + i * 4);
    }
}

// ---------------------------------------------------------------- 6) W fp32 -> fp16
__global__ __launch_bounds__(256)
void build_W(const float* __restrict__ W, __half* __restrict__ Wh) {
    int idx = blockIdx.x * 256 + threadIdx.x;
    if (idx >= COUT * 224) return;
    ((uint16_t*)Wh)[idx] = hbits(W[idx]);
}

// ---------------------------------------------------------------- 7) mix GEMM (HMMA fp16)
// tmp[(n,o,l), v] = bias[o] + zT[(n,l,v), :224] @ Wh  (7 chunks of 32)
#define MIX_WP 232                          // ws pitch (u16)
#define MIX_WBYTES (COUT * MIX_WP * 2)      // 29696
#define MIX_APITCH 80
#define MIX_ASTAGE (128 * MIX_APITCH)       // 10240
#define MIX_SMEM (MIX_WBYTES + 33792)       // 63488

__global__ __launch_bounds__(256, 2)
void mix_gemm(const __half* __restrict__ zT, const __half* __restrict__ Wh,
              const float* __restrict__ bias, float* __restrict__ tmp) {
    extern __shared__ char smem[];
    const uint32_t sb = smem_u32(smem);
    uint16_t* ws = (uint16_t*)smem;                        // [64][232]
    const uint32_t asb = sb + MIX_WBYTES;
    const int tid = threadIdx.x;
    const int wid = tid >> 5, lane = tid & 31;
    const int bm = blockIdx.x * 128;
    const int wm = wid & 3, wn = wid >> 2;

    for (int i = tid; i < COUT * 112; i += 256) {
        int o = i / 112, kk = (i % 112) * 2;
        *(uint32_t*)(ws + o * MIX_WP + kk) =
            *(const uint32_t*)((const uint16_t*)Wh + o * 224 + kk);
    }

    float acc[2][4][4];
    #pragma unroll
    for (int i = 0; i < 2; i++)
        #pragma unroll
        for (int j = 0; j < 4; j++)
            #pragma unroll
            for (int q = 0; q < 4; q++) acc[i][j][q] = 0.f;

    auto load_stage = [&](int slot, int chunk) {
        const uint32_t base = asb + slot * MIX_ASTAGE;
        const int ac = chunk * 32;
        #pragma unroll
        for (int i = 0; i < 2; i++) {
            int c = tid + i * 256;
            int row = c >> 2, c16 = c & 3;
            cp_async16(base + row * MIX_APITCH + c16 * 16,
                       zT + ((size_t)bm + row) * ZTC + ac + c16 * 8);
        }
        asm volatile("cp.async.commit_group;" ::: "memory");
    };

    load_stage(0, 0);
    load_stage(1, 1);
    __syncthreads();

    const int lrow = lane & 15;
    const int lkh  = (lane >> 4) << 3;
    const int og   = lane >> 2;
    const int kq   = (lane & 3) * 2;

    for (int it = 0; it < 7; it++) {
        if (it + 2 < 7) load_stage((it + 2) % 3, it + 2);
        int rem = 6 - it;
        if (rem >= 2)      asm volatile("cp.async.wait_group 2;" ::: "memory");
        else if (rem == 1) asm volatile("cp.async.wait_group 1;" ::: "memory");
        else               asm volatile("cp.async.wait_group 0;" ::: "memory");
        __syncthreads();

        const uint32_t abase = asb + (it % 3) * MIX_ASTAGE;
        const int bc = it * 32;

        #pragma unroll
        for (int ks = 0; ks < 2; ks++) {
            uint32_t a_regs[2][4];
            #pragma unroll
            for (int mf = 0; mf < 2; mf++) {
                int row = wm * 32 + mf * 16 + lrow;
                ldsm4(a_regs[mf], abase + row * MIX_APITCH + (ks * 16 + lkh) * 2);
            }
            #pragma unroll
            for (int nq = 0; nq < 4; nq++) {
                int o = wn * 32 + nq * 8 + og;
                int k = bc + ks * 16 + kq;
                uint32_t b0 = *(uint32_t*)(ws + o * MIX_WP + k);
                uint32_t b1 = *(uint32_t*)(ws + o * MIX_WP + k + 8);
                #pragma unroll
                for (int mf = 0; mf < 2; mf++)
                    mma16816(acc[mf][nq], a_regs[mf], b0, b1);
            }
        }
        __syncthreads();
    }

    // epilogue: stage [o][w] (pitch 132) then coalesced tmp writes
    float* s2 = (float*)(smem + MIX_WBYTES);
    const int gid = lane >> 2, tig = lane & 3;
    #pragma unroll
    for (int mf = 0; mf < 2; mf++) {
        int r0 = wm * 32 + mf * 16 + gid;
        #pragma unroll
        for (int nq = 0; nq < 4; nq++) {
            int o = wn * 32 + nq * 8 + tig * 2;
            float* d = acc[mf][nq];
            s2[o * 132 + r0] = d[0];       s2[(o + 1) * 132 + r0] = d[1];
            s2[o * 132 + r0 + 8] = d[2];   s2[(o + 1) * 132 + r0 + 8] = d[3];
        }
    }
    __syncthreads();

    const int nl = bm >> 9;
    const int n = nl / 13, l = nl - n * 13;
    const int wbase = bm & 511;
    #pragma unroll
    for (int i = 0; i < 8; i++) {
        int idx = tid + i * 256;
        int o = idx >> 5, q = idx & 31;
        float4 v = *(float4*)(s2 + o * 132 + q * 4);
        float bo = bias[o];
        v.x += bo; v.y += bo; v.z += bo; v.w += bo;
        *(float4*)(tmp + (((size_t)n * COUT + o) * L_ + l) * V_ + wbase + q * 4) = v;
    }
}

// ---------------------------------------------------------------- 8) tmp[n][o][l][v] -> out[n][o][v][l]
__global__ __launch_bounds__(256)
void out_transpose(const float* __restrict__ tmp, float* __restrict__ out) {
    __shared__ float s[13 * 520];
    const int no  = blockIdx.x;
    const int tid = threadIdx.x;
    const float* src = tmp + (size_t)no * (V_ * L_);
    for (int i = tid; i < V_ * L_; i += 256)
        s[(i >> 9) * 520 + (i & 511)] = src[i];
    __syncthreads();
    float* dst = out + (size_t)no * (V_ * L_);
    #pragma unroll
    for (int i = 0; i < 26; i++) {
        int addr = i * 256 + tid;          // contiguous store addr = v*13+l
        int v = addr / 13, l = addr - v * 13;
        dst[addr] = s[l * 520 + v];
    }
}

// ---------------------------------------------------------------- launcher
extern "C" void kernel_launch(void* const* d_in, const int* in_sizes, int n_in,
                              void* d_out, int out_size) {
    const float* x  = (const float*)d_in[0];
    const float* a0 = (const float*)d_in[1];
    const float* a1 = (const float*)d_in[2];
    const float* a2 = (const float*)d_in[3];
    const float* W  = (const float*)d_in[4];
    const float* b  = (const float*)d_in[5];
    float* out = (float*)d_out;

    float *pw, *tmp;
    __half *Ah, *Bh, *zT, *Wh;
    cudaGetSymbolAddress((void**)&pw,  g_pow);
    cudaGetSymbolAddress((void**)&tmp, g_tmp);
    cudaGetSymbolAddress((void**)&Ah,  g_Ah);
    cudaGetSymbolAddress((void**)&Bh,  g_Bh);
    cudaGetSymbolAddress((void**)&zT,  g_zT);
    cudaGetSymbolAddress((void**)&Wh,  g_Wh);

    cudaFuncSetAttribute(mma_gemm, cudaFuncAttributeMaxDynamicSharedMemorySize, GEMM_SMEM);
    cudaFuncSetAttribute(mix_gemm, cudaFuncAttributeMaxDynamicSharedMemorySize, MIX_SMEM);

    pow_kernel<<<dim3(8, 8, 3), 256>>>(a0, a1, a2, pw);
    build_A<<<B_ * C_, 256>>>(x, Ah);
    build_B<<<(NB * 512) / 256, 256>>>(a0, a1, a2, pw, Bh);
    seed_zT<<<B_ * L_, 512>>>(Ah, zT);
    build_W<<<(COUT * 224 + 255) / 256, 256>>>(W, Wh);

    mma_gemm<<<dim3(NB / BNg, M_ROWS / BMg), 256, GEMM_SMEM>>>(Ah, Bh, zT);

    mix_gemm<<<NLW / 128, 256, MIX_SMEM>>>(zT, Wh, b, tmp);
    out_transpose<<<B_ * COUT, 256>>>(tmp, out);
}

// round 9
// speedup vs baseline: 4.8450x; 1.3726x over previous
#include <cuda_runtime.h>
#include <cuda_fp16.h>
#include <cstdint>

// ---------------------------------------------------------------- constants
#define B_    64
#define C_    32
#define V_    512
#define L_    13
#define COUT  64
#define M_ROWS 26624            // B_*C_*L_  rows ordered (n,l,c)
#define NB    3072              // 6 support-powers * 512
#define KA    512               // A cols: xh only
#define KB    512               // B cols: ah only
#define NLW   425984            // 832 (n,l) * 512 w
#define ZTC   224               // zT cols: hi only (7 chan blocks x 32)

// ---------------------------------------------------------------- scratch
__device__ __half g_Ah[(size_t)M_ROWS * KA];      // 27.3 MB
__device__ __half g_Bh[(size_t)NB * KB];          // 3.1 MB
__device__ __half g_zT[(size_t)NLW * ZTC];        // 190.8 MB
__device__ __half g_Wh[COUT * 224];
__device__ float  g_pow[3 * V_ * V_];
__device__ float  g_tmp[(size_t)B_ * COUT * L_ * V_];  // [n][o][l][v]

// ---------------------------------------------------------------- utils
__device__ __forceinline__ uint32_t smem_u32(const void* p) {
    uint32_t a;
    asm("{ .reg .u64 t; cvta.to.shared.u64 t, %1; cvt.u32.u64 %0, t; }" : "=r"(a) : "l"(p));
    return a;
}
__device__ __forceinline__ void cp_async16(uint32_t s, const void* g) {
    asm volatile("cp.async.cg.shared.global [%0], [%1], 16;" :: "r"(s), "l"(g));
}
__device__ __forceinline__ void ldsm4(uint32_t* r, uint32_t addr) {
    asm volatile("ldmatrix.sync.aligned.m8n8.x4.shared.b16 {%0,%1,%2,%3}, [%4];"
                 : "=r"(r[0]), "=r"(r[1]), "=r"(r[2]), "=r"(r[3]) : "r"(addr));
}
__device__ __forceinline__ void mma16816(float* d, const uint32_t* a, uint32_t b0, uint32_t b1) {
    asm volatile(
        "mma.sync.aligned.m16n8k16.row.col.f32.f16.f16.f32 "
        "{%0,%1,%2,%3}, {%4,%5,%6,%7}, {%8,%9}, {%0,%1,%2,%3};"
        : "+f"(d[0]), "+f"(d[1]), "+f"(d[2]), "+f"(d[3])
        : "r"(a[0]), "r"(a[1]), "r"(a[2]), "r"(a[3]), "r"(b0), "r"(b1));
}
#define SW128(off) ((off) ^ (((off) >> 3) & 0x70))

__device__ __forceinline__ uint16_t hbits(float f) {
    __half h = __float2half_rn(f);
    return *reinterpret_cast<uint16_t*>(&h);
}

// ---------------------------------------------------------------- 1) a^2 (fp32)
__global__ __launch_bounds__(256)
void pow_kernel(const float* __restrict__ a0, const float* __restrict__ a1,
                const float* __restrict__ a2, float* __restrict__ out) {
    const float* A = (blockIdx.z == 0) ? a0 : (blockIdx.z == 1 ? a1 : a2);
    float* Cc = out + (size_t)blockIdx.z * V_ * V_;
    __shared__ float As[16][64];
    __shared__ float Bs[16][68];
    const int tid = threadIdx.x;
    const int bm = blockIdx.y * 64, bn = blockIdx.x * 64;
    const int tx = tid & 15, ty = tid >> 4;
    float acc[4][4] = {};
    for (int kb = 0; kb < 512; kb += 16) {
        float4 va = *(const float4*)(A + (size_t)(bm + (tid >> 2)) * 512 + kb + (tid & 3) * 4);
        As[(tid & 3) * 4 + 0][tid >> 2] = va.x;
        As[(tid & 3) * 4 + 1][tid >> 2] = va.y;
        As[(tid & 3) * 4 + 2][tid >> 2] = va.z;
        As[(tid & 3) * 4 + 3][tid >> 2] = va.w;
        *(float4*)&Bs[tid >> 4][(tid & 15) * 4] =
            *(const float4*)(A + (size_t)(kb + (tid >> 4)) * 512 + bn + (tid & 15) * 4);
        __syncthreads();
        #pragma unroll
        for (int k = 0; k < 16; k++) {
            float wf[4], hf[4];
            #pragma unroll
            for (int i = 0; i < 4; i++) wf[i] = As[k][ty * 4 + i];
            #pragma unroll
            for (int j = 0; j < 4; j++) hf[j] = Bs[k][tx * 4 + j];
            #pragma unroll
            for (int i = 0; i < 4; i++)
                #pragma unroll
                for (int j = 0; j < 4; j++) acc[i][j] = fmaf(wf[i], hf[j], acc[i][j]);
        }
        __syncthreads();
    }
    #pragma unroll
    for (int i = 0; i < 4; i++)
        #pragma unroll
        for (int j = 0; j < 4; j++)
            Cc[(size_t)(bm + ty * 4 + i) * 512 + bn + tx * 4 + j] = acc[i][j];
}

// ---------------------------------------------------------------- 2) A rows (n,l,c): xh
__global__ __launch_bounds__(256)
void build_A(const float* __restrict__ x, __half* __restrict__ Ah) {
    __shared__ float s[V_ * L_];
    const int nc = blockIdx.x;              // n*32 + c
    const int n = nc >> 5, c = nc & 31;
    const int tid = threadIdx.x;
    const float* slab = x + (size_t)nc * (V_ * L_);
    for (int i = tid; i < V_ * L_; i += 256) s[i] = slab[i];
    __syncthreads();
    for (int e = tid; e < V_ * L_; e += 256) {
        int l = e >> 9, v = e & 511;
        float val = s[v * L_ + l];
        size_t m = ((size_t)n * L_ + l) * 32 + c;
        ((uint16_t*)Ah)[m * KA + v] = hbits(val);
    }
}

// ---------------------------------------------------------------- 3) B (hi only)
__global__ __launch_bounds__(256)
void build_B(const float* __restrict__ a0, const float* __restrict__ a1,
             const float* __restrict__ a2, const float* __restrict__ pw,
             __half* __restrict__ Bh) {
    int idx = blockIdx.x * 256 + threadIdx.x;
    if (idx >= NB * 512) return;
    int v = idx & 511;
    int j = idx >> 9;                // B row: p*512 + w
    int p = j >> 9;
    int w = j & 511;
    const float* P = (p & 1) ? (pw + (size_t)(p >> 1) * V_ * V_)
                             : (p == 0 ? a0 : (p == 2 ? a1 : a2));
    ((uint16_t*)Bh)[(size_t)j * KB + v] = hbits(P[(size_t)v * 512 + w]);
}

// ---------------------------------------------------------------- 4) seed zT block 0 (x hi)
__global__ __launch_bounds__(512)
void seed_zT(const __half* __restrict__ Ah, __half* __restrict__ zT) {
    __shared__ uint32_t s32[32 * 257];      // [c][256 u32], pitch 257
    const int nl = blockIdx.x;
    const int tid = threadIdx.x;
    for (int i = tid; i < 32 * 256; i += 512) {
        int c = i >> 8, kk = i & 255;
        const uint32_t* pa = (const uint32_t*)(Ah + ((size_t)nl * 32 + c) * KA);
        s32[c * 257 + kk] = pa[kk];
    }
    __syncthreads();
    const int v = tid;
    uint32_t hi[16];
    #pragma unroll
    for (int i = 0; i < 16; i++) {
        uint32_t w0 = s32[(2*i) * 257 + (v >> 1)];
        uint32_t w1 = s32[(2*i+1) * 257 + (v >> 1)];
        uint16_t h0 = (v & 1) ? (uint16_t)(w0 >> 16) : (uint16_t)w0;
        uint16_t h1 = (v & 1) ? (uint16_t)(w1 >> 16) : (uint16_t)w1;
        hi[i] = (uint32_t)h0 | ((uint32_t)h1 << 16);
    }
    char* dst = (char*)zT + ((size_t)nl * 512 + v) * (ZTC * 2);
    #pragma unroll
    for (int i = 0; i < 4; i++)
        *(uint4*)(dst + i * 16) = *(uint4*)(hi + i * 4);
}

// ---------------------------------------------------------------- 5) GEMM1 (HMMA fp16)
#define BMg 128
#define BNg 128
#define BKg 64
#define NSTG 3
#define STG_A (BMg * BKg * 2)
#define STG_B (BNg * BKg * 2)
#define STG_BYTES (STG_A + STG_B)          // 32768
#define GEMM_SMEM (NSTG * STG_BYTES)       // 98304
#define KITERS 8                            // KA/BKg

__global__ __launch_bounds__(256, 2)
void mma_gemm(const __half* __restrict__ A, const __half* __restrict__ Bm,
              __half* __restrict__ zT) {
    extern __shared__ char smem[];
    const uint32_t sb = smem_u32(smem);
    const int tid = threadIdx.x;
    const int wid = tid >> 5, lane = tid & 31;
    const int bm = blockIdx.y * BMg;       // N-fastest launch for A L2 reuse
    const int bn = blockIdx.x * BNg;
    const int wm = wid & 3;
    const int wn = wid >> 2;

    float acc[2][8][4];
    #pragma unroll
    for (int i = 0; i < 2; i++)
        #pragma unroll
        for (int j = 0; j < 8; j++)
            #pragma unroll
            for (int q = 0; q < 4; q++) acc[i][j][q] = 0.f;

    auto load_stage = [&](int slot, int it) {
        const uint32_t abase = sb + slot * STG_BYTES;
        const uint32_t bbase = abase + STG_A;
        const __half* Ag = A + (size_t)bm * KA + it * BKg;
        const __half* Bg = Bm + (size_t)bn * KB + it * BKg;
        #pragma unroll
        for (int i = 0; i < 4; i++) {
            int c = tid + i * 256;
            int row = c >> 3, c16 = c & 7;
            uint32_t off = (uint32_t)(row * 128 + c16 * 16);
            cp_async16(abase + SW128(off), Ag + (size_t)row * KA + c16 * 8);
        }
        #pragma unroll
        for (int i = 0; i < 4; i++) {
            int c = tid + i * 256;
            int row = c >> 3, c16 = c & 7;
            uint32_t off = (uint32_t)(row * 128 + c16 * 16);
            cp_async16(bbase + SW128(off), Bg + (size_t)row * KB + c16 * 8);
        }
        asm volatile("cp.async.commit_group;" ::: "memory");
    };

    load_stage(0, 0);
    load_stage(1, 1);

    for (int it = 0; it < KITERS; it++) {
        if (it + 2 < KITERS) load_stage((it + 2) % NSTG, it + 2);
        int rem = KITERS - 1 - it;
        if (rem >= 2)      asm volatile("cp.async.wait_group 2;" ::: "memory");
        else if (rem == 1) asm volatile("cp.async.wait_group 1;" ::: "memory");
        else               asm volatile("cp.async.wait_group 0;" ::: "memory");
        __syncthreads();

        const uint32_t abase = sb + (it % NSTG) * STG_BYTES;
        const uint32_t bbase = abase + STG_A;
        const int lrow = lane & 15;
        const int lkh  = (lane >> 4) << 3;

        #pragma unroll
        for (int ks = 0; ks < 4; ks++) {
            const int k0 = ks * 16;
            uint32_t a_regs[2][4];
            #pragma unroll
            for (int mf = 0; mf < 2; mf++) {
                int row = wm * 32 + mf * 16 + lrow;
                ldsm4(a_regs[mf], abase + SW128((uint32_t)(row * 128 + (k0 + lkh) * 2)));
            }
            uint32_t b_regs[4][4];
            #pragma unroll
            for (int nq = 0; nq < 4; nq++) {
                int row = wn * 64 + nq * 16 + lrow;
                ldsm4(b_regs[nq], bbase + SW128((uint32_t)(row * 128 + (k0 + lkh) * 2)));
            }
            #pragma unroll
            for (int mf = 0; mf < 2; mf++)
                #pragma unroll
                for (int nq = 0; nq < 4; nq++) {
                    mma16816(acc[mf][nq * 2 + 0], a_regs[mf], b_regs[nq][0], b_regs[nq][2]);
                    mma16816(acc[mf][nq * 2 + 1], a_regs[mf], b_regs[nq][1], b_regs[nq][3]);
                }
        }
        __syncthreads();
    }

    // epilogue: acc -> smem fp32 [128][129] -> zT fp16 hi, c-transposed
    float* s = (float*)smem;
    const int gid = lane >> 2, tig = lane & 3;
    #pragma unroll
    for (int mf = 0; mf < 2; mf++) {
        int r0 = wm * 32 + mf * 16 + gid;
        #pragma unroll
        for (int nf = 0; nf < 8; nf++) {
            int cc = wn * 64 + nf * 8 + tig * 2;
            float* d = acc[mf][nf];
            s[r0 * 129 + cc] = d[0];       s[r0 * 129 + cc + 1] = d[1];
            s[(r0 + 8) * 129 + cc] = d[2]; s[(r0 + 8) * 129 + cc + 1] = d[3];
        }
    }
    __syncthreads();

    const int p = bn >> 9;
    const int wbase = bn & 511;
    const int nlbase = bm >> 5;
    #pragma unroll
    for (int rep = 0; rep < 2; rep++) {
        int rw = tid + rep * 256;
        int nlg = rw >> 7, w = rw & 127;
        uint32_t hi[16];
        #pragma unroll
        for (int i = 0; i < 16; i++) {
            float v0 = s[(nlg * 32 + 2*i) * 129 + w];
            float v1 = s[(nlg * 32 + 2*i + 1) * 129 + w];
            hi[i] = (uint32_t)hbits(v0) | ((uint32_t)hbits(v1) << 16);
        }
        size_t gr = ((size_t)(nlbase + nlg) * 512) + wbase + w;
        char* dst = (char*)zT + gr * (ZTC * 2) + (p + 1) * 64;
        #pragma unroll
        for (int i = 0; i < 4; i++)
            *(uint4*)(dst + i * 16) = *(uint4*)(hi + i * 4);
    }
}

// ---------------------------------------------------------------- 6) W fp32 -> fp16
__global__ __launch_bounds__(256)
void build_W(const float* __restrict__ W, __half* __restrict__ Wh) {
    int idx = blockIdx.x * 256 + threadIdx.x;
    if (idx >= COUT * 224) return;
    ((uint16_t*)Wh)[idx] = hbits(W[idx]);
}

// ---------------------------------------------------------------- 7) mix GEMM (HMMA fp16)
#define MIX_WP 232                          // ws pitch (u16)
#define MIX_WBYTES (COUT * MIX_WP * 2)      // 29696
#define MIX_APITCH 80
#define MIX_ASTAGE (128 * MIX_APITCH)       // 10240
#define MIX_SMEM (MIX_WBYTES + 33792)       // 63488

__global__ __launch_bounds__(256, 2)
void mix_gemm(const __half* __restrict__ zT, const __half* __restrict__ Wh,
              const float* __restrict__ bias, float* __restrict__ tmp) {
    extern __shared__ char smem[];
    const uint32_t sb = smem_u32(smem);
    uint16_t* ws = (uint16_t*)smem;                        // [64][232]
    const uint32_t asb = sb + MIX_WBYTES;
    const int tid = threadIdx.x;
    const int wid = tid >> 5, lane = tid & 31;
    const int bm = blockIdx.x * 128;
    const int wm = wid & 3, wn = wid >> 2;

    for (int i = tid; i < COUT * 112; i += 256) {
        int o = i / 112, kk = (i % 112) * 2;
        *(uint32_t*)(ws + o * MIX_WP + kk) =
            *(const uint32_t*)((const uint16_t*)Wh + o * 224 + kk);
    }

    float acc[2][4][4];
    #pragma unroll
    for (int i = 0; i < 2; i++)
        #pragma unroll
        for (int j = 0; j < 4; j++)
            #pragma unroll
            for (int q = 0; q < 4; q++) acc[i][j][q] = 0.f;

    auto load_stage = [&](int slot, int chunk) {
        const uint32_t base = asb + slot * MIX_ASTAGE;
        const int ac = chunk * 32;
        #pragma unroll
        for (int i = 0; i < 2; i++) {
            int c = tid + i * 256;
            int row = c >> 2, c16 = c & 3;
            cp_async16(base + row * MIX_APITCH + c16 * 16,
                       zT + ((size_t)bm + row) * ZTC + ac + c16 * 8);
        }
        asm volatile("cp.async.commit_group;" ::: "memory");
    };

    load_stage(0, 0);
    load_stage(1, 1);
    __syncthreads();

    const int lrow = lane & 15;
    const int lkh  = (lane >> 4) << 3;
    const int og   = lane >> 2;
    const int kq   = (lane & 3) * 2;

    for (int it = 0; it < 7; it++) {
        if (it + 2 < 7) load_stage((it + 2) % 3, it + 2);
        int rem = 6 - it;
        if (rem >= 2)      asm volatile("cp.async.wait_group 2;" ::: "memory");
        else if (rem == 1) asm volatile("cp.async.wait_group 1;" ::: "memory");
        else               asm volatile("cp.async.wait_group 0;" ::: "memory");
        __syncthreads();

        const uint32_t abase = asb + (it % 3) * MIX_ASTAGE;
        const int bc = it * 32;

        #pragma unroll
        for (int ks = 0; ks < 2; ks++) {
            uint32_t a_regs[2][4];
            #pragma unroll
            for (int mf = 0; mf < 2; mf++) {
                int row = wm * 32 + mf * 16 + lrow;
                ldsm4(a_regs[mf], abase + row * MIX_APITCH + (ks * 16 + lkh) * 2);
            }
            #pragma unroll
            for (int nq = 0; nq < 4; nq++) {
                int o = wn * 32 + nq * 8 + og;
                int k = bc + ks * 16 + kq;
                uint32_t b0 = *(uint32_t*)(ws + o * MIX_WP + k);
                uint32_t b1 = *(uint32_t*)(ws + o * MIX_WP + k + 8);
                #pragma unroll
                for (int mf = 0; mf < 2; mf++)
                    mma16816(acc[mf][nq], a_regs[mf], b0, b1);
            }
        }
        __syncthreads();
    }

    // epilogue: stage [o][w] (pitch 132) then coalesced tmp writes
    float* s2 = (float*)(smem + MIX_WBYTES);
    const int gid = lane >> 2, tig = lane & 3;
    #pragma unroll
    for (int mf = 0; mf < 2; mf++) {
        int r0 = wm * 32 + mf * 16 + gid;
        #pragma unroll
        for (int nq = 0; nq < 4; nq++) {
            int o = wn * 32 + nq * 8 + tig * 2;
            float* d = acc[mf][nq];
            s2[o * 132 + r0] = d[0];       s2[(o + 1) * 132 + r0] = d[1];
            s2[o * 132 + r0 + 8] = d[2];   s2[(o + 1) * 132 + r0 + 8] = d[3];
        }
    }
    __syncthreads();

    const int nl = bm >> 9;
    const int n = nl / 13, l = nl - n * 13;
    const int wbase = bm & 511;
    #pragma unroll
    for (int i = 0; i < 8; i++) {
        int idx = tid + i * 256;
        int o = idx >> 5, q = idx & 31;
        float4 v = *(float4*)(s2 + o * 132 + q * 4);
        float bo = bias[o];
        v.x += bo; v.y += bo; v.z += bo; v.w += bo;
        *(float4*)(tmp + (((size_t)n * COUT + o) * L_ + l) * V_ + wbase + q * 4) = v;
    }
}

// ---------------------------------------------------------------- 8) tmp[n][o][l][v] -> out[n][o][v][l]
__global__ __launch_bounds__(256)
void out_transpose(const float* __restrict__ tmp, float* __restrict__ out) {
    __shared__ float s[13 * 520];
    const int no  = blockIdx.x;
    const int tid = threadIdx.x;
    const float* src = tmp + (size_t)no * (V_ * L_);
    for (int i = tid; i < V_ * L_; i += 256)
        s[(i >> 9) * 520 + (i & 511)] = src[i];
    __syncthreads();
    float* dst = out + (size_t)no * (V_ * L_);
    #pragma unroll
    for (int i = 0; i < 26; i++) {
        int addr = i * 256 + tid;          // contiguous store addr = v*13+l
        int v = addr / 13, l = addr - v * 13;
        dst[addr] = s[l * 520 + v];
    }
}

// ---------------------------------------------------------------- launcher
extern "C" void kernel_launch(void* const* d_in, const int* in_sizes, int n_in,
                              void* d_out, int out_size) {
    const float* x  = (const float*)d_in[0];
    const float* a0 = (const float*)d_in[1];
    const float* a1 = (const float*)d_in[2];
    const float* a2 = (const float*)d_in[3];
    const float* W  = (const float*)d_in[4];
    const float* b  = (const float*)d_in[5];
    float* out = (float*)d_out;

    float *pw, *tmp;
    __half *Ah, *Bh, *zT, *Wh;
    cudaGetSymbolAddress((void**)&pw,  g_pow);
    cudaGetSymbolAddress((void**)&tmp, g_tmp);
    cudaGetSymbolAddress((void**)&Ah,  g_Ah);
    cudaGetSymbolAddress((void**)&Bh,  g_Bh);
    cudaGetSymbolAddress((void**)&zT,  g_zT);
    cudaGetSymbolAddress((void**)&Wh,  g_Wh);

    cudaFuncSetAttribute(mma_gemm, cudaFuncAttributeMaxDynamicSharedMemorySize, GEMM_SMEM);
    cudaFuncSetAttribute(mix_gemm, cudaFuncAttributeMaxDynamicSharedMemorySize, MIX_SMEM);

    pow_kernel<<<dim3(8, 8, 3), 256>>>(a0, a1, a2, pw);
    build_A<<<B_ * C_, 256>>>(x, Ah);
    build_B<<<(NB * 512) / 256, 256>>>(a0, a1, a2, pw, Bh);
    seed_zT<<<B_ * L_, 512>>>(Ah, zT);
    build_W<<<(COUT * 224 + 255) / 256, 256>>>(W, Wh);

    mma_gemm<<<dim3(NB / BNg, M_ROWS / BMg), 256, GEMM_SMEM>>>(Ah, Bh, zT);

    mix_gemm<<<NLW / 128, 256, MIX_SMEM>>>(zT, Wh, b, tmp);
    out_transpose<<<B_ * COUT, 256>>>(tmp, out);
}